// round 2
// baseline (speedup 1.0000x reference)
#include <cuda_runtime.h>
#include <cuda_bf16.h>
#include <stdint.h>
#include <math.h>

// Problem constants
#define DN 256      // dim
#define LL 4        // memory bank len
#define NH 8        // heads
#define HD 32       // head dim
#define NMAX 100000

// ---------------- device globals (scratch; no allocations allowed) ----------
__device__ int g_cnts[2];              // [0]=valid count, [1]=saved count
__device__ int g_vlist[NMAX];
__device__ int g_slist[NMAX];

// ---------------- helpers ---------------------------------------------------
__device__ __forceinline__ float warpSum(float x) {
#pragma unroll
    for (int o = 16; o > 0; o >>= 1) x += __shfl_xor_sync(0xffffffffu, x, o);
    return x;
}

// Gather 32 rows of 256 floats into smem tile s[32][256].
// Warp w loads rows 4w..4w+3; lane loads 2 float4s per row.
__device__ __forceinline__ void load_rows(const float* __restrict__ g, float* s,
                                          const int* rowid, size_t rowStride,
                                          size_t rowOff) {
    int w = threadIdx.x >> 5, lane = threadIdx.x & 31;
#pragma unroll
    for (int i = 0; i < 4; i++) {
        int r = w * 4 + i;
        const float4* src = (const float4*)(g + (size_t)rowid[r] * rowStride + rowOff);
        float4* dst = (float4*)(s + r * DN);
        dst[lane]      = src[lane];
        dst[lane + 32] = src[lane + 32];
    }
}

// Y[32,256] = X[32,256] * W^T, W is [256 out][256 in] row-major.
// Thread t: rc=t&31, rr=t>>5. Owns rows rr*4..rr*4+3, cols rc+32j (j=0..7).
// Wc smem layout: Wc[o*33 + k] for a 32-wide k-chunk -> conflict-free reads
// (lane stride 33 -> bank stride 1) and conflict-free writes (lane stride 1).
__device__ __noinline__ void gemm_tile(const float* __restrict__ Wg,
                                       const float* __restrict__ X,
                                       float* Wc, float* Y) {
    const int t = threadIdx.x, rc = t & 31, rr = t >> 5;
    float acc[4][8];
#pragma unroll
    for (int i = 0; i < 4; i++)
#pragma unroll
        for (int j = 0; j < 8; j++) acc[i][j] = 0.f;

#pragma unroll 1
    for (int kc = 0; kc < DN; kc += 32) {
        __syncthreads();   // protect Wc from previous chunk's readers
        // warp rr loads 32 consecutive out-rows, lane = k index
#pragma unroll
        for (int i = 0; i < 32; i++) {
            int o = (rr << 5) + i;
            Wc[o * 33 + rc] = Wg[o * DN + kc + rc];
        }
        __syncthreads();
#pragma unroll 8
        for (int k = 0; k < 32; k++) {
            float x0 = X[(rr * 4 + 0) * DN + kc + k];
            float x1 = X[(rr * 4 + 1) * DN + kc + k];
            float x2 = X[(rr * 4 + 2) * DN + kc + k];
            float x3 = X[(rr * 4 + 3) * DN + kc + k];
#pragma unroll
            for (int j = 0; j < 8; j++) {
                float w = Wc[(rc + (j << 5)) * 33 + k];
                acc[0][j] = fmaf(x0, w, acc[0][j]);
                acc[1][j] = fmaf(x1, w, acc[1][j]);
                acc[2][j] = fmaf(x2, w, acc[2][j]);
                acc[3][j] = fmaf(x3, w, acc[3][j]);
            }
        }
    }
    __syncthreads();  // allow Y to alias X safely
#pragma unroll
    for (int i = 0; i < 4; i++)
#pragma unroll
        for (int j = 0; j < 8; j++)
            Y[(rr * 4 + i) * DN + rc + (j << 5)] = acc[i][j];
}

// ---------------- kernel A: flags, new_mask, invalid-row copy, compaction ---
// mem_padding_mask arrives as int32 (bool -> int32 in the harness).
__global__ __launch_bounds__(256) void kA(const float* __restrict__ emb,
                                          const float* __restrict__ scores,
                                          const int* __restrict__ maskg,
                                          float* __restrict__ out, int n) {
    int w = threadIdx.x >> 5, lane = threadIdx.x & 31;
    int row = blockIdx.x * 8 + w;
    if (row >= n) return;
    float sc = scores[row];
    bool saved = sc > 0.f;
    bool valid = (maskg[(size_t)row * LL + (LL - 1)] == 0);

    float* omask = out + (size_t)n * DN + (size_t)n * (LL * DN);
    if (lane < LL) {
        int cur = maskg[(size_t)row * LL + lane];
        int nm = saved ? ((lane < LL - 1) ? maskg[(size_t)row * LL + lane + 1]
                                          : 0)
                       : cur;
        omask[(size_t)row * LL + lane] = nm ? 1.f : 0.f;
    }
    if (lane == 0) {
        if (valid) { int i = atomicAdd(&g_cnts[0], 1); g_vlist[i] = row; }
        if (saved) { int i = atomicAdd(&g_cnts[1], 1); g_slist[i] = row; }
    }
    if (!valid) {
        // new_emb = output_embedding for invalid rows
        const float4* s = (const float4*)(emb + (size_t)row * DN);
        float4* d = (float4*)(out + (size_t)row * DN);
        d[lane]      = s[lane];
        d[lane + 32] = s[lane + 32];
    }
}

// ---------------- kernel B: fused transformer over valid rows ---------------
// smem layout (bytes): Wc 33792 | xb 32768 | B1 | B2 | B3 | ys (4x32768)
//                    | lg 4096 | att 4096 | rowid 128 | msk 512
#define KB_SMEM (33792 + 5 * 32768 + 4096 + 4096 + 128 + 512)

__global__ __launch_bounds__(256) void kB(
    const float* __restrict__ emb, const float* __restrict__ bank,
    const int* __restrict__ maskg,
    const float* __restrict__ inw, const float* __restrict__ inb,
    const float* __restrict__ outw, const float* __restrict__ outb,
    const float* __restrict__ fc1w, const float* __restrict__ fc1b,
    const float* __restrict__ fc2w, const float* __restrict__ fc2b,
    const float* __restrict__ g1, const float* __restrict__ b1,
    const float* __restrict__ g2, const float* __restrict__ b2,
    float* __restrict__ out, int n) {
    extern __shared__ char sm[];
    float* Wc = (float*)sm;                       // 256*33 floats
    float* xb = (float*)(sm + 33792);
    float* B1 = xb + 32 * DN;
    float* B2 = B1 + 32 * DN;
    float* B3 = B2 + 32 * DN;
    float* ys = B3 + 32 * DN;
    float* lg = ys + 32 * DN;                     // [32][8][4]
    float* att = lg + 32 * NH * LL;               // [32][8][4]
    int* rowid = (int*)(att + 32 * NH * LL);      // [32]
    int* msk = rowid + 32;                        // [32][4] int32

    const int cnt = g_cnts[0];
    const int tile = blockIdx.x;
    if (tile * 32 >= cnt) return;
    const int nrows = min(32, cnt - tile * 32);
    const int t = threadIdx.x, lane = t & 31, w = t >> 5;

    if (t < 32) rowid[t] = g_vlist[tile * 32 + min(t, nrows - 1)];
    __syncthreads();
    if (t < 32 * LL) msk[t] = maskg[(size_t)rowid[t >> 2] * LL + (t & 3)];
    load_rows(emb, xb, rowid, DN, 0);
    __syncthreads();

    // ---- q projection ----
    gemm_tile(inw, xb, Wc, ys);
    // q epilogue (own mapping, no sync needed before reading own ys)
#pragma unroll
    for (int i = 0; i < 4; i++)
#pragma unroll
        for (int j = 0; j < 8; j++) {
            int r = w * 4 + i, c = lane + (j << 5);
            B1[r * DN + c] = ys[r * DN + c] + inb[c];
        }
    __syncthreads();

    // ---- k projections + logits ----
    for (int l = 0; l < LL; l++) {
        load_rows(bank, B2, rowid, LL * DN, (size_t)l * DN);
        __syncthreads();
        gemm_tile(inw + DN * DN, B2, Wc, ys);
        __syncthreads();
        {
            int r = t >> 3, h = t & 7;
            float s = 0.f;
#pragma unroll 8
            for (int d0 = 0; d0 < HD; d0++) {
                int d = (d0 + t) & 31;            // rotate -> conflict-free
                int idx = r * DN + h * HD + d;
                s += B1[idx] * (ys[idx] + inb[DN + h * HD + d]);
            }
            lg[(r * NH + h) * LL + l] = s;
        }
        __syncthreads();
    }

    // ---- softmax over L with padding mask ----
    {
        int r = t >> 3, h = t & 7;
        const float sc = 0.17677669529663687f;    // 1/sqrt(32)
        float v[LL]; float mx = -1e30f;
#pragma unroll
        for (int l = 0; l < LL; l++) {
            float x = msk[r * LL + l] ? -1e9f : lg[(r * NH + h) * LL + l] * sc;
            v[l] = x; mx = fmaxf(mx, x);
        }
        float s = 0.f;
#pragma unroll
        for (int l = 0; l < LL; l++) { v[l] = expf(v[l] - mx); s += v[l]; }
        float inv = 1.f / s;
#pragma unroll
        for (int l = 0; l < LL; l++) att[(r * NH + h) * LL + l] = v[l] * inv;
    }
    __syncthreads();

    // ---- v projections + weighted context ----
#pragma unroll
    for (int i = 0; i < 4; i++)
#pragma unroll
        for (int j = 0; j < 8; j++)
            B3[(w * 4 + i) * DN + lane + (j << 5)] = 0.f;
    for (int l = 0; l < LL; l++) {
        __syncthreads();
        load_rows(bank, B2, rowid, LL * DN, (size_t)l * DN);
        __syncthreads();
        gemm_tile(inw + 2 * DN * DN, B2, Wc, ys);
        // epilogue: own-mapping ys; head index h == j since c = lane + 32j
#pragma unroll
        for (int i = 0; i < 4; i++) {
            int r = w * 4 + i;
#pragma unroll
            for (int j = 0; j < 8; j++) {
                int c = lane + (j << 5);
                B3[r * DN + c] += att[(r * NH + j) * LL + l] *
                                  (ys[r * DN + c] + inb[2 * DN + c]);
            }
        }
    }
    __syncthreads();

    // ---- out projection + residual + LN1 -> B1 (e1) ----
    gemm_tile(outw, B3, Wc, ys);
#pragma unroll
    for (int i = 0; i < 4; i++) {
        int r = w * 4 + i;
        float v[8]; float ps = 0.f;
#pragma unroll
        for (int j = 0; j < 8; j++) {
            int c = lane + (j << 5);
            v[j] = ys[r * DN + c] + outb[c] + xb[r * DN + c];
            ps += v[j];
        }
        float mu = warpSum(ps) * (1.f / DN);
        float ps2 = 0.f;
#pragma unroll
        for (int j = 0; j < 8; j++) { float d = v[j] - mu; ps2 += d * d; }
        float rstd = rsqrtf(warpSum(ps2) * (1.f / DN) + 1e-5f);
#pragma unroll
        for (int j = 0; j < 8; j++) {
            int c = lane + (j << 5);
            B1[r * DN + c] = (v[j] - mu) * rstd * g1[c] + b1[c];
        }
    }
    __syncthreads();

    // ---- FFN ----
    gemm_tile(fc1w, B1, Wc, ys);
#pragma unroll
    for (int i = 0; i < 4; i++)
#pragma unroll
        for (int j = 0; j < 8; j++) {
            int r = w * 4 + i, c = lane + (j << 5);
            B2[r * DN + c] = fmaxf(ys[r * DN + c] + fc1b[c], 0.f);
        }
    __syncthreads();
    gemm_tile(fc2w, B2, Wc, ys);

    // ---- residual + LN2 -> scatter to out ----
#pragma unroll
    for (int i = 0; i < 4; i++) {
        int r = w * 4 + i;
        float v[8]; float ps = 0.f;
#pragma unroll
        for (int j = 0; j < 8; j++) {
            int c = lane + (j << 5);
            v[j] = ys[r * DN + c] + fc2b[c] + B1[r * DN + c];
            ps += v[j];
        }
        float mu = warpSum(ps) * (1.f / DN);
        float ps2 = 0.f;
#pragma unroll
        for (int j = 0; j < 8; j++) { float d = v[j] - mu; ps2 += d * d; }
        float rstd = rsqrtf(warpSum(ps2) * (1.f / DN) + 1e-5f);
        if (r < nrows) {
            size_t row = (size_t)rowid[r];
#pragma unroll
            for (int j = 0; j < 8; j++) {
                int c = lane + (j << 5);
                out[row * DN + c] = (v[j] - mu) * rstd * g2[c] + b2[c];
            }
        }
    }
}

// ---------------- kernel C: bank shift/copy (all rows; saved slot3 left to D)
__global__ __launch_bounds__(256) void kC(const float* __restrict__ scores,
                                          const float* __restrict__ bank,
                                          float* __restrict__ out, int n) {
    int w = threadIdx.x >> 5, lane = threadIdx.x & 31;
    int row = blockIdx.x * 8 + w;
    if (row >= n) return;
    bool saved = scores[row] > 0.f;
    const float4* b = (const float4*)(bank + (size_t)row * (LL * DN));
    float4* ob = (float4*)(out + (size_t)n * DN + (size_t)row * (LL * DN));
#pragma unroll
    for (int l = 0; l < LL; l++) {
        int src = saved ? l + 1 : l;
        if (src < LL) {
            ob[l * 64 + lane]      = b[src * 64 + lane];
            ob[l * 64 + lane + 32] = b[src * 64 + lane + 32];
        }
    }
}

// ---------------- kernel D: save_proj for saved rows -> bank slot L-1 -------
#define KD_SMEM (33792 + 32768 + 32768 + 128)
__global__ __launch_bounds__(256) void kD(const float* __restrict__ savew,
                                          const float* __restrict__ saveb,
                                          float* __restrict__ out, int n) {
    extern __shared__ char sm[];
    float* Wc = (float*)sm;
    float* xs = (float*)(sm + 33792);
    float* ys = xs + 32 * DN;
    int* rowid = (int*)(ys + 32 * DN);

    const int cnt = g_cnts[1];
    const int tile = blockIdx.x;
    if (tile * 32 >= cnt) return;
    const int nrows = min(32, cnt - tile * 32);
    const int t = threadIdx.x, lane = t & 31, w = t >> 5;
    if (t < 32) rowid[t] = g_slist[tile * 32 + min(t, nrows - 1)];
    __syncthreads();
    load_rows(out, xs, rowid, DN, 0);   // new_emb (already final for all rows)
    __syncthreads();
    gemm_tile(savew, xs, Wc, ys);
    float* obank = out + (size_t)n * DN;
#pragma unroll
    for (int i = 0; i < 4; i++) {
        int r = w * 4 + i;
        if (r < nrows) {
            size_t row = (size_t)rowid[r];
#pragma unroll
            for (int j = 0; j < 8; j++) {
                int c = lane + (j << 5);
                obank[row * (LL * DN) + (LL - 1) * DN + c] =
                    ys[r * DN + c] + saveb[c];
            }
        }
    }
}

// ---------------- host launch ----------------------------------------------
extern "C" void kernel_launch(void* const* d_in, const int* in_sizes, int n_in,
                              void* d_out, int out_size) {
    const float* emb    = (const float*)d_in[0];
    const float* scores = (const float*)d_in[1];
    const float* bank   = (const float*)d_in[2];
    const int*   maskg  = (const int*)d_in[3];
    const float* savew = (const float*)d_in[4];
    const float* saveb = (const float*)d_in[5];
    const float* inw   = (const float*)d_in[6];
    const float* inb   = (const float*)d_in[7];
    const float* outw  = (const float*)d_in[8];
    const float* outb  = (const float*)d_in[9];
    const float* fc1w  = (const float*)d_in[10];
    const float* fc1b  = (const float*)d_in[11];
    const float* fc2w  = (const float*)d_in[12];
    const float* fc2b  = (const float*)d_in[13];
    const float* g1    = (const float*)d_in[14];
    const float* b1    = (const float*)d_in[15];
    const float* g2    = (const float*)d_in[16];
    const float* b2    = (const float*)d_in[17];
    float* out = (float*)d_out;

    int n = in_sizes[1];   // scores length == N

    void* cntaddr = nullptr;
    cudaGetSymbolAddress(&cntaddr, g_cnts);
    cudaMemsetAsync(cntaddr, 0, 2 * sizeof(int));

    cudaFuncSetAttribute(kB, cudaFuncAttributeMaxDynamicSharedMemorySize, KB_SMEM);
    cudaFuncSetAttribute(kD, cudaFuncAttributeMaxDynamicSharedMemorySize, KD_SMEM);

    kA<<<(n + 7) / 8, 256>>>(emb, scores, maskg, out, n);
    kB<<<(n + 31) / 32, 256, KB_SMEM>>>(emb, bank, maskg, inw, inb, outw, outb,
                                        fc1w, fc1b, fc2w, fc2b, g1, b1, g2, b2,
                                        out, n);
    kC<<<(n + 7) / 8, 256>>>(scores, bank, out, n);
    kD<<<(n + 31) / 32, 256, KD_SMEM>>>(savew, saveb, out, n);
}

// round 3
// speedup vs baseline: 1.1871x; 1.1871x over previous
#include <cuda_runtime.h>
#include <cuda_bf16.h>
#include <stdint.h>
#include <math.h>

#define DN 256      // dim
#define LL 4        // memory bank len
#define NH 8        // heads
#define HD 32       // head dim
#define NMAX 100000
#define WCP 68      // Wc row stride in words (68 mod 32 == 4 -> conflict-free LDS.128/STS.128)

// ---------------- device globals ----------------
__device__ int g_cnts[2];              // [0]=valid count, [1]=saved count
__device__ int g_vlist[NMAX];
__device__ int g_slist[NMAX];

// ---------------- helpers ----------------
__device__ __forceinline__ uint64_t ffma2(uint64_t a, uint64_t b, uint64_t c) {
    uint64_t d;
    asm("fma.rn.f32x2 %0, %1, %2, %3;" : "=l"(d) : "l"(a), "l"(b), "l"(c));
    return d;
}
__device__ __forceinline__ float red2(uint64_t v) {
    float lo = __uint_as_float((unsigned)(v & 0xffffffffull));
    float hi = __uint_as_float((unsigned)(v >> 32));
    return lo + hi;
}
__device__ __forceinline__ float segSum8(float x) {
#pragma unroll
    for (int o = 4; o > 0; o >>= 1) x += __shfl_xor_sync(0xffffffffu, x, o, 8);
    return x;
}

// Gather 32 rows of 256 floats into smem tile s[32][256].
__device__ __forceinline__ void load_rows(const float* __restrict__ g, float* s,
                                          const int* rowid, size_t rowStride,
                                          size_t rowOff) {
    int w = threadIdx.x >> 5, lane = threadIdx.x & 31;
#pragma unroll
    for (int i = 0; i < 4; i++) {
        int r = w * 4 + i;
        const float4* src = (const float4*)(g + (size_t)rowid[r] * rowStride + rowOff);
        float4* dst = (float4*)(s + r * DN);
        dst[lane]      = src[lane];
        dst[lane + 32] = src[lane + 32];
    }
}

// Y[32,256] = X[32,256] * W^T  (W row-major [256 out][256 in]).
// 256 threads. warp w: rg=w>>1 owns rows rg*8..+7, cg=w&1 owns cols cg*128+lane+32m.
// Packed-over-k fp32 (fma.rn.f32x2). Y may alias X (writes after tail barrier).
// Caller must __syncthreads() before any cross-thread read of Y.
__device__ __forceinline__ void gemm_tile(const float* __restrict__ Wg,
                                          const float* __restrict__ X,
                                          float* __restrict__ Wc,
                                          float* __restrict__ Y) {
    const int t = threadIdx.x, lane = t & 31, w = t >> 5;
    const int rg = w >> 1, cg = w & 1;
    const float* Xr = X + (rg * 8) * DN;

    uint64_t acc2[8][4];
#pragma unroll
    for (int i = 0; i < 8; i++)
#pragma unroll
        for (int m = 0; m < 4; m++) acc2[i][m] = 0ull;

#pragma unroll 1
    for (int kc = 0; kc < DN; kc += 64) {
        __syncthreads();                      // Wc free of previous readers
        {   // stage 256x64 W chunk, o-major stride WCP
            int ko = (lane & 15) * 4;
            int oo = (w << 5) + (lane >> 4);
#pragma unroll
            for (int i = 0; i < 16; i++) {
                int o = oo + i * 2;
                float4 v = *(const float4*)&Wg[o * DN + kc + ko];
                *(float4*)&Wc[o * WCP + ko] = v;
            }
        }
        __syncthreads();
#pragma unroll 2
        for (int kk = 0; kk < 64; kk += 4) {
            ulonglong2 wv0 = *(const ulonglong2*)&Wc[(cg * 128 + lane) * WCP + kk];
            ulonglong2 wv1 = *(const ulonglong2*)&Wc[(cg * 128 + lane + 32) * WCP + kk];
            ulonglong2 wv2 = *(const ulonglong2*)&Wc[(cg * 128 + lane + 64) * WCP + kk];
            ulonglong2 wv3 = *(const ulonglong2*)&Wc[(cg * 128 + lane + 96) * WCP + kk];
#pragma unroll
            for (int i = 0; i < 8; i++) {
                ulonglong2 xv = *(const ulonglong2*)&Xr[i * DN + kc + kk];
                acc2[i][0] = ffma2(xv.x, wv0.x, acc2[i][0]);
                acc2[i][1] = ffma2(xv.x, wv1.x, acc2[i][1]);
                acc2[i][2] = ffma2(xv.x, wv2.x, acc2[i][2]);
                acc2[i][3] = ffma2(xv.x, wv3.x, acc2[i][3]);
                acc2[i][0] = ffma2(xv.y, wv0.y, acc2[i][0]);
                acc2[i][1] = ffma2(xv.y, wv1.y, acc2[i][1]);
                acc2[i][2] = ffma2(xv.y, wv2.y, acc2[i][2]);
                acc2[i][3] = ffma2(xv.y, wv3.y, acc2[i][3]);
            }
        }
    }
    __syncthreads();                           // all X reads done; Y may alias X
#pragma unroll
    for (int i = 0; i < 8; i++)
#pragma unroll
        for (int m = 0; m < 4; m++)
            Y[(rg * 8 + i) * DN + cg * 128 + lane + (m << 5)] = red2(acc2[i][m]);
}

// ---------------- kernel A: flags, new_mask, invalid-row copy, compaction ---
__global__ __launch_bounds__(256) void kA(const float* __restrict__ emb,
                                          const float* __restrict__ scores,
                                          const int* __restrict__ maskg,
                                          float* __restrict__ out, int n) {
    int w = threadIdx.x >> 5, lane = threadIdx.x & 31;
    int row = blockIdx.x * 8 + w;
    if (row >= n) return;
    bool saved = scores[row] > 0.f;
    bool valid = (maskg[(size_t)row * LL + (LL - 1)] == 0);

    float* omask = out + (size_t)n * DN + (size_t)n * (LL * DN);
    if (lane < LL) {
        int cur = maskg[(size_t)row * LL + lane];
        int nm = saved ? ((lane < LL - 1) ? maskg[(size_t)row * LL + lane + 1] : 0)
                       : cur;
        omask[(size_t)row * LL + lane] = nm ? 1.f : 0.f;
    }
    if (lane == 0) {
        if (valid) { int i = atomicAdd(&g_cnts[0], 1); g_vlist[i] = row; }
        if (saved) { int i = atomicAdd(&g_cnts[1], 1); g_slist[i] = row; }
    }
    if (!valid) {
        const float4* s = (const float4*)(emb + (size_t)row * DN);
        float4* d = (float4*)(out + (size_t)row * DN);
        d[lane]      = s[lane];
        d[lane + 32] = s[lane + 32];
    }
}

// ---------------- kernel B: fused transformer over valid rows ---------------
// smem float offsets
#define WC_F  0
#define XB_F  17408
#define B1_F  25600
#define B2_F  33792
#define B3_F  41984
#define LG_F  50176
#define ATT_F 51200
#define SB_F  52224            /* 10 x 256 bias/gain vectors */
#define RID_F 54784
#define MSK_F 54816
#define KB_SMEM (54944 * 4)

__global__ __launch_bounds__(256, 1) void kB(
    const float* __restrict__ emb, const float* __restrict__ bank,
    const int* __restrict__ maskg,
    const float* __restrict__ inw, const float* __restrict__ inb,
    const float* __restrict__ outw, const float* __restrict__ outb,
    const float* __restrict__ fc1w, const float* __restrict__ fc1b,
    const float* __restrict__ fc2w, const float* __restrict__ fc2b,
    const float* __restrict__ g1, const float* __restrict__ b1,
    const float* __restrict__ g2, const float* __restrict__ b2,
    float* __restrict__ out, int n) {
    extern __shared__ float sm[];
    float* Wc = sm + WC_F;
    float* xb = sm + XB_F;
    float* B1 = sm + B1_F;
    float* B2 = sm + B2_F;
    float* B3 = sm + B3_F;
    float* lg = sm + LG_F;                 // [32][8][4]
    float* att = sm + ATT_F;               // [32][8][4]
    float* sb = sm + SB_F;
    int* rowid = (int*)(sm + RID_F);
    int* msk = (int*)(sm + MSK_F);

    const int cnt = g_cnts[0];
    const int tile = blockIdx.x;
    if (tile * 32 >= cnt) return;
    const int nrows = min(32, cnt - tile * 32);
    const int t = threadIdx.x, lane = t & 31, w = t >> 5;
    const int rg = w >> 1, cg = w & 1;

    if (t < 32) rowid[t] = g_vlist[tile * 32 + min(t, nrows - 1)];
    // preload biases/gains into smem
    sb[t]        = inb[t];
    sb[256 + t]  = inb[256 + t];
    sb[512 + t]  = inb[512 + t];
    sb[768 + t]  = outb[t];
    sb[1024 + t] = fc1b[t];
    sb[1280 + t] = fc2b[t];
    sb[1536 + t] = g1[t];
    sb[1792 + t] = b1[t];
    sb[2048 + t] = g2[t];
    sb[2304 + t] = b2[t];
    __syncthreads();
    if (t < 32 * LL) msk[t] = maskg[(size_t)rowid[t >> 2] * LL + (t & 3)];
    load_rows(emb, xb, rowid, DN, 0);

    // ---- q projection (raw; biases folded into logits) ----
    gemm_tile(inw, xb, Wc, B1);

    // ---- k projections + logits ----
    for (int l = 0; l < LL; l++) {
        __syncthreads();                       // B1/B2 readers done
        load_rows(bank, B2, rowid, LL * DN, (size_t)l * DN);
        gemm_tile(inw + DN * DN, B2, Wc, B2);  // in-place
        __syncthreads();
        {
            int r = t >> 3, h = t & 7;
            float s = 0.f;
#pragma unroll 8
            for (int d0 = 0; d0 < HD; d0++) {
                int d = (d0 + t) & 31;
                int col = h * HD + d;
                int idx = r * DN + col;
                s += (B1[idx] + sb[col]) * (B2[idx] + sb[256 + col]);
            }
            lg[(r * NH + h) * LL + l] = s;
        }
    }

    // ---- softmax over L (own cells; no sync needed vs logits) ----
    {
        int r = t >> 3, h = t & 7;
        const float sc = 0.17677669529663687f;     // 1/sqrt(32)
        float v[LL]; float mx = -1e30f;
#pragma unroll
        for (int l = 0; l < LL; l++) {
            float x = msk[r * LL + l] ? -1e9f : lg[(r * NH + h) * LL + l] * sc;
            v[l] = x; mx = fmaxf(mx, x);
        }
        float s = 0.f;
#pragma unroll
        for (int l = 0; l < LL; l++) { v[l] = expf(v[l] - mx); s += v[l]; }
        float inv = 1.f / s;
#pragma unroll
        for (int l = 0; l < LL; l++) att[(r * NH + h) * LL + l] = v[l] * inv;
    }
    // zero ctx accumulator
    for (int i = t; i < 32 * DN; i += 256) B3[i] = 0.f;

    // ---- v projections + weighted context ----
    for (int l = 0; l < LL; l++) {
        __syncthreads();                      // att visible; B2 readers done
        load_rows(bank, B2, rowid, LL * DN, (size_t)l * DN);
        gemm_tile(inw + 2 * DN * DN, B2, Wc, B2);
        // own-cell accumulate (gemm mapping); h == c>>5
#pragma unroll
        for (int i = 0; i < 8; i++) {
            int r = rg * 8 + i;
#pragma unroll
            for (int m = 0; m < 4; m++) {
                int c = cg * 128 + lane + (m << 5);
                B3[r * DN + c] += att[(r * NH + (c >> 5)) * LL + l] *
                                  (B2[r * DN + c] + sb[512 + c]);
            }
        }
    }

    // ---- out projection + residual + LN1 -> B1 ----
    gemm_tile(outw, B3, Wc, B2);
    __syncthreads();
    {
        int r = t >> 3, c0 = (t & 7) * 4;
        float4 vv[8]; float s1 = 0.f, s2 = 0.f;
#pragma unroll
        for (int j = 0; j < 8; j++) {
            int c = c0 + j * 32;
            float4 a = *(const float4*)&B2[r * DN + c];
            float4 rr = *(const float4*)&xb[r * DN + c];
            float4 bb = *(const float4*)&sb[768 + c];
            float x0 = a.x + bb.x + rr.x, x1 = a.y + bb.y + rr.y;
            float x2 = a.z + bb.z + rr.z, x3 = a.w + bb.w + rr.w;
            vv[j] = make_float4(x0, x1, x2, x3);
            s1 += x0 + x1 + x2 + x3;
            s2 += x0 * x0 + x1 * x1 + x2 * x2 + x3 * x3;
        }
        s1 = segSum8(s1); s2 = segSum8(s2);
        float mu = s1 * (1.f / DN);
        float var = fmaxf(s2 * (1.f / DN) - mu * mu, 0.f);
        float rstd = rsqrtf(var + 1e-5f);
#pragma unroll
        for (int j = 0; j < 8; j++) {
            int c = c0 + j * 32;
            float4 gg = *(const float4*)&sb[1536 + c];
            float4 bb = *(const float4*)&sb[1792 + c];
            float4 o;
            o.x = (vv[j].x - mu) * rstd * gg.x + bb.x;
            o.y = (vv[j].y - mu) * rstd * gg.y + bb.y;
            o.z = (vv[j].z - mu) * rstd * gg.z + bb.z;
            o.w = (vv[j].w - mu) * rstd * gg.w + bb.w;
            *(float4*)&B1[r * DN + c] = o;
        }
    }

    // ---- FFN ----
    gemm_tile(fc1w, B1, Wc, B2);
    // relu + bias, own cells
#pragma unroll
    for (int i = 0; i < 8; i++) {
        int r = rg * 8 + i;
#pragma unroll
        for (int m = 0; m < 4; m++) {
            int c = cg * 128 + lane + (m << 5);
            B2[r * DN + c] = fmaxf(B2[r * DN + c] + sb[1024 + c], 0.f);
        }
    }
    gemm_tile(fc2w, B2, Wc, B3);
    __syncthreads();

    // ---- residual + LN2 -> scatter to gmem ----
    {
        int r = t >> 3, c0 = (t & 7) * 4;
        float4 vv[8]; float s1 = 0.f, s2 = 0.f;
#pragma unroll
        for (int j = 0; j < 8; j++) {
            int c = c0 + j * 32;
            float4 a = *(const float4*)&B3[r * DN + c];
            float4 rr = *(const float4*)&B1[r * DN + c];
            float4 bb = *(const float4*)&sb[1280 + c];
            float x0 = a.x + bb.x + rr.x, x1 = a.y + bb.y + rr.y;
            float x2 = a.z + bb.z + rr.z, x3 = a.w + bb.w + rr.w;
            vv[j] = make_float4(x0, x1, x2, x3);
            s1 += x0 + x1 + x2 + x3;
            s2 += x0 * x0 + x1 * x1 + x2 * x2 + x3 * x3;
        }
        s1 = segSum8(s1); s2 = segSum8(s2);
        float mu = s1 * (1.f / DN);
        float var = fmaxf(s2 * (1.f / DN) - mu * mu, 0.f);
        float rstd = rsqrtf(var + 1e-5f);
        if (r < nrows) {
            size_t row = (size_t)rowid[r];
#pragma unroll
            for (int j = 0; j < 8; j++) {
                int c = c0 + j * 32;
                float4 gg = *(const float4*)&sb[2048 + c];
                float4 bb = *(const float4*)&sb[2304 + c];
                float4 o;
                o.x = (vv[j].x - mu) * rstd * gg.x + bb.x;
                o.y = (vv[j].y - mu) * rstd * gg.y + bb.y;
                o.z = (vv[j].z - mu) * rstd * gg.z + bb.z;
                o.w = (vv[j].w - mu) * rstd * gg.w + bb.w;
                *(float4*)&out[row * DN + c] = o;
            }
        }
    }
}

// ---------------- kernel C: bank shift/copy ----------------
__global__ __launch_bounds__(256) void kC(const float* __restrict__ scores,
                                          const float* __restrict__ bank,
                                          float* __restrict__ out, int n) {
    int w = threadIdx.x >> 5, lane = threadIdx.x & 31;
    int row = blockIdx.x * 8 + w;
    if (row >= n) return;
    bool saved = scores[row] > 0.f;
    const float4* b = (const float4*)(bank + (size_t)row * (LL * DN));
    float4* ob = (float4*)(out + (size_t)n * DN + (size_t)row * (LL * DN));
#pragma unroll
    for (int l = 0; l < LL; l++) {
        int src = saved ? l + 1 : l;
        if (src < LL) {
            ob[l * 64 + lane]      = b[src * 64 + lane];
            ob[l * 64 + lane + 32] = b[src * 64 + lane + 32];
        }
    }
}

// ---------------- kernel D: save_proj for saved rows -> bank slot L-1 -------
#define KD_XS_F 17408
#define KD_RID_F (17408 + 8192)
#define KD_SMEM ((17408 + 8192 + 32) * 4)
__global__ __launch_bounds__(256) void kD(const float* __restrict__ savew,
                                          const float* __restrict__ saveb,
                                          float* __restrict__ out, int n) {
    extern __shared__ float sm[];
    float* Wc = sm;
    float* xs = sm + KD_XS_F;
    int* rowid = (int*)(sm + KD_RID_F);

    const int cnt = g_cnts[1];
    const int tile = blockIdx.x;
    if (tile * 32 >= cnt) return;
    const int nrows = min(32, cnt - tile * 32);
    const int t = threadIdx.x, lane = t & 31, w = t >> 5;
    const int rg = w >> 1, cg = w & 1;
    if (t < 32) rowid[t] = g_slist[tile * 32 + min(t, nrows - 1)];
    __syncthreads();
    load_rows(out, xs, rowid, DN, 0);     // new_emb (final for all rows)
    gemm_tile(savew, xs, Wc, xs);         // in-place
    float* obank = out + (size_t)n * DN;
#pragma unroll
    for (int i = 0; i < 8; i++) {
        int r = rg * 8 + i;
        if (r < nrows) {
            size_t row = (size_t)rowid[r];
#pragma unroll
            for (int m = 0; m < 4; m++) {
                int c = cg * 128 + lane + (m << 5);
                obank[row * (LL * DN) + (LL - 1) * DN + c] =
                    xs[r * DN + c] + saveb[c];
            }
        }
    }
}

// ---------------- host launch ----------------
extern "C" void kernel_launch(void* const* d_in, const int* in_sizes, int n_in,
                              void* d_out, int out_size) {
    const float* emb    = (const float*)d_in[0];
    const float* scores = (const float*)d_in[1];
    const float* bank   = (const float*)d_in[2];
    const int*   maskg  = (const int*)d_in[3];
    const float* savew = (const float*)d_in[4];
    const float* saveb = (const float*)d_in[5];
    const float* inw   = (const float*)d_in[6];
    const float* inb   = (const float*)d_in[7];
    const float* outw  = (const float*)d_in[8];
    const float* outb  = (const float*)d_in[9];
    const float* fc1w  = (const float*)d_in[10];
    const float* fc1b  = (const float*)d_in[11];
    const float* fc2w  = (const float*)d_in[12];
    const float* fc2b  = (const float*)d_in[13];
    const float* g1    = (const float*)d_in[14];
    const float* b1    = (const float*)d_in[15];
    const float* g2    = (const float*)d_in[16];
    const float* b2    = (const float*)d_in[17];
    float* out = (float*)d_out;

    int n = in_sizes[1];   // scores length == N

    void* cntaddr = nullptr;
    cudaGetSymbolAddress(&cntaddr, g_cnts);
    cudaMemsetAsync(cntaddr, 0, 2 * sizeof(int));

    cudaFuncSetAttribute(kB, cudaFuncAttributeMaxDynamicSharedMemorySize, KB_SMEM);
    cudaFuncSetAttribute(kD, cudaFuncAttributeMaxDynamicSharedMemorySize, KD_SMEM);

    kA<<<(n + 7) / 8, 256>>>(emb, scores, maskg, out, n);
    kB<<<(n + 31) / 32, 256, KB_SMEM>>>(emb, bank, maskg, inw, inb, outw, outb,
                                        fc1w, fc1b, fc2w, fc2b, g1, b1, g2, b2,
                                        out, n);
    kC<<<(n + 7) / 8, 256>>>(scores, bank, out, n);
    kD<<<(n + 31) / 32, 256, KD_SMEM>>>(savew, saveb, out, n);
}

// round 5
// speedup vs baseline: 1.2434x; 1.0475x over previous
#include <cuda_runtime.h>
#include <cuda_bf16.h>
#include <stdint.h>
#include <math.h>

#define DN 256      // dim
#define LL 4        // memory bank len
#define NH 8        // heads
#define HD 32       // head dim
#define NMAX 100000
#define WCP 68      // Wc row stride in words (68 mod 32 == 4 -> conflict-free LDS.128/STS.128)

// ---------------- device globals ----------------
__device__ int g_cnts[2];              // [0]=valid count, [1]=saved count
__device__ int g_vlist[NMAX];
__device__ int g_slist[NMAX];

// ---------------- helpers ----------------
__device__ __forceinline__ uint64_t ffma2(uint64_t a, uint64_t b, uint64_t c) {
    uint64_t d;
    asm("fma.rn.f32x2 %0, %1, %2, %3;" : "=l"(d) : "l"(a), "l"(b), "l"(c));
    return d;
}
__device__ __forceinline__ float red2(uint64_t v) {
    float lo = __uint_as_float((unsigned)(v & 0xffffffffull));
    float hi = __uint_as_float((unsigned)(v >> 32));
    return lo + hi;
}
__device__ __forceinline__ float segSum8(float x) {
#pragma unroll
    for (int o = 4; o > 0; o >>= 1) x += __shfl_xor_sync(0xffffffffu, x, o, 8);
    return x;
}

// Gather 32 rows of 256 floats into smem tile s[32][256].
__device__ __forceinline__ void load_rows(const float* __restrict__ g, float* s,
                                          const int* rowid, size_t rowStride,
                                          size_t rowOff) {
    int w = threadIdx.x >> 5, lane = threadIdx.x & 31;
#pragma unroll
    for (int i = 0; i < 4; i++) {
        int r = w * 4 + i;
        const float4* src = (const float4*)(g + (size_t)rowid[r] * rowStride + rowOff);
        float4* dst = (float4*)(s + r * DN);
        dst[lane]      = src[lane];
        dst[lane + 32] = src[lane + 32];
    }
}

// Y[32,256] = X[32,256] * W^T  (W row-major [256 out][256 in]).
// 256 threads. warp w: rg=w>>1 owns rows rg*8..+7, cg=w&1 owns cols cg*128+lane+32m.
// Packed-over-k fp32 (fma.rn.f32x2). Y may alias X (writes after tail barrier).
// Caller must __syncthreads() before any cross-thread read of Y.
__device__ __forceinline__ void gemm_tile(const float* __restrict__ Wg,
                                          const float* __restrict__ X,
                                          float* __restrict__ Wc,
                                          float* __restrict__ Y) {
    const int t = threadIdx.x, lane = t & 31, w = t >> 5;
    const int rg = w >> 1, cg = w & 1;
    const float* Xr = X + (rg * 8) * DN;

    uint64_t acc2[8][4];
#pragma unroll
    for (int i = 0; i < 8; i++)
#pragma unroll
        for (int m = 0; m < 4; m++) acc2[i][m] = 0ull;

#pragma unroll 1
    for (int kc = 0; kc < DN; kc += 64) {
        __syncthreads();                      // Wc free of previous readers
        {   // stage 256x64 W chunk, o-major stride WCP
            int ko = (lane & 15) * 4;
            int oo = (w << 5) + (lane >> 4);
#pragma unroll
            for (int i = 0; i < 16; i++) {
                int o = oo + i * 2;
                float4 v = *(const float4*)&Wg[o * DN + kc + ko];
                *(float4*)&Wc[o * WCP + ko] = v;
            }
        }
        __syncthreads();
#pragma unroll 2
        for (int kk = 0; kk < 64; kk += 4) {
            ulonglong2 wv0 = *(const ulonglong2*)&Wc[(cg * 128 + lane) * WCP + kk];
            ulonglong2 wv1 = *(const ulonglong2*)&Wc[(cg * 128 + lane + 32) * WCP + kk];
            ulonglong2 wv2 = *(const ulonglong2*)&Wc[(cg * 128 + lane + 64) * WCP + kk];
            ulonglong2 wv3 = *(const ulonglong2*)&Wc[(cg * 128 + lane + 96) * WCP + kk];
#pragma unroll
            for (int i = 0; i < 8; i++) {
                ulonglong2 xv = *(const ulonglong2*)&Xr[i * DN + kc + kk];
                acc2[i][0] = ffma2(xv.x, wv0.x, acc2[i][0]);
                acc2[i][1] = ffma2(xv.x, wv1.x, acc2[i][1]);
                acc2[i][2] = ffma2(xv.x, wv2.x, acc2[i][2]);
                acc2[i][3] = ffma2(xv.x, wv3.x, acc2[i][3]);
                acc2[i][0] = ffma2(xv.y, wv0.y, acc2[i][0]);
                acc2[i][1] = ffma2(xv.y, wv1.y, acc2[i][1]);
                acc2[i][2] = ffma2(xv.y, wv2.y, acc2[i][2]);
                acc2[i][3] = ffma2(xv.y, wv3.y, acc2[i][3]);
            }
        }
    }
    __syncthreads();                           // all X reads done; Y may alias X
#pragma unroll
    for (int i = 0; i < 8; i++)
#pragma unroll
        for (int m = 0; m < 4; m++)
            Y[(rg * 8 + i) * DN + cg * 128 + lane + (m << 5)] = red2(acc2[i][m]);
}

// ---------------- kernel A: flags, new_mask, invalid-row copy, compaction ---
__global__ __launch_bounds__(256) void kA(const float* __restrict__ emb,
                                          const float* __restrict__ scores,
                                          const int* __restrict__ maskg,
                                          float* __restrict__ out, int n) {
    int w = threadIdx.x >> 5, lane = threadIdx.x & 31;
    int row = blockIdx.x * 8 + w;
    if (row >= n) return;
    bool saved = scores[row] > 0.f;
    bool valid = (maskg[(size_t)row * LL + (LL - 1)] == 0);

    float* omask = out + (size_t)n * DN + (size_t)n * (LL * DN);
    if (lane < LL) {
        int cur = maskg[(size_t)row * LL + lane];
        int nm = saved ? ((lane < LL - 1) ? maskg[(size_t)row * LL + lane + 1] : 0)
                       : cur;
        omask[(size_t)row * LL + lane] = nm ? 1.f : 0.f;
    }
    if (lane == 0) {
        if (valid) { int i = atomicAdd(&g_cnts[0], 1); g_vlist[i] = row; }
        if (saved) { int i = atomicAdd(&g_cnts[1], 1); g_slist[i] = row; }
    }
    if (!valid) {
        const float4* s = (const float4*)(emb + (size_t)row * DN);
        float4* d = (float4*)(out + (size_t)row * DN);
        d[lane]      = s[lane];
        d[lane + 32] = s[lane + 32];
    }
}

// ---------------- kernel B: fused transformer over valid rows ---------------
// smem float offsets
#define WC_F  0
#define XB_F  17408
#define B1_F  25600
#define B2_F  33792
#define B3_F  41984
#define LG_F  50176
#define ATT_F 51200
#define SB_F  52224            /* 10 x 256 bias/gain vectors */
#define RID_F 54784
#define MSK_F 54816
#define KB_SMEM (54944 * 4)

__global__ __launch_bounds__(256, 1) void kB(
    const float* __restrict__ emb, const float* __restrict__ bank,
    const int* __restrict__ maskg,
    const float* __restrict__ inw, const float* __restrict__ inb,
    const float* __restrict__ outw, const float* __restrict__ outb,
    const float* __restrict__ fc1w, const float* __restrict__ fc1b,
    const float* __restrict__ fc2w, const float* __restrict__ fc2b,
    const float* __restrict__ g1, const float* __restrict__ b1,
    const float* __restrict__ g2, const float* __restrict__ b2,
    float* __restrict__ out, int n) {
    extern __shared__ float sm[];
    float* Wc = sm + WC_F;
    float* xb = sm + XB_F;
    float* B1 = sm + B1_F;
    float* B2 = sm + B2_F;
    float* B3 = sm + B3_F;
    float* lg = sm + LG_F;                 // [32][8][4]
    float* att = sm + ATT_F;               // [32][8][4]
    float* sb = sm + SB_F;
    int* rowid = (int*)(sm + RID_F);
    int* msk = (int*)(sm + MSK_F);

    const int cnt = g_cnts[0];
    const int tile = blockIdx.x;
    if (tile * 32 >= cnt) return;
    const int nrows = min(32, cnt - tile * 32);
    const int t = threadIdx.x, lane = t & 31, w = t >> 5;
    const int rg = w >> 1, cg = w & 1;

    if (t < 32) rowid[t] = g_vlist[tile * 32 + min(t, nrows - 1)];
    // preload biases/gains into smem
    sb[t]        = inb[t];
    sb[256 + t]  = inb[256 + t];
    sb[512 + t]  = inb[512 + t];
    sb[768 + t]  = outb[t];
    sb[1024 + t] = fc1b[t];
    sb[1280 + t] = fc2b[t];
    sb[1536 + t] = g1[t];
    sb[1792 + t] = b1[t];
    sb[2048 + t] = g2[t];
    sb[2304 + t] = b2[t];
    __syncthreads();
    if (t < 32 * LL) msk[t] = maskg[(size_t)rowid[t >> 2] * LL + (t & 3)];
    load_rows(emb, xb, rowid, DN, 0);

    // ---- q projection (raw; biases folded into logits) ----
    gemm_tile(inw, xb, Wc, B1);

    // ---- k projections + logits ----
    for (int l = 0; l < LL; l++) {
        __syncthreads();                       // B1/B2 readers done
        load_rows(bank, B2, rowid, LL * DN, (size_t)l * DN);
        gemm_tile(inw + DN * DN, B2, Wc, B2);  // in-place
        __syncthreads();
        {
            int r = t >> 3, h = t & 7;
            float s = 0.f;
#pragma unroll 8
            for (int d0 = 0; d0 < HD; d0++) {
                int d = (d0 + t) & 31;
                int col = h * HD + d;
                int idx = r * DN + col;
                s += (B1[idx] + sb[col]) * (B2[idx] + sb[256 + col]);
            }
            lg[(r * NH + h) * LL + l] = s;
        }
    }

    // ---- softmax over L (own cells; no sync needed vs logits) ----
    {
        int r = t >> 3, h = t & 7;
        const float sc = 0.17677669529663687f;     // 1/sqrt(32)
        float v[LL]; float mx = -1e30f;
#pragma unroll
        for (int l = 0; l < LL; l++) {
            float x = msk[r * LL + l] ? -1e9f : lg[(r * NH + h) * LL + l] * sc;
            v[l] = x; mx = fmaxf(mx, x);
        }
        float s = 0.f;
#pragma unroll
        for (int l = 0; l < LL; l++) { v[l] = expf(v[l] - mx); s += v[l]; }
        float inv = 1.f / s;
#pragma unroll
        for (int l = 0; l < LL; l++) att[(r * NH + h) * LL + l] = v[l] * inv;
    }
    // zero ctx accumulator
    for (int i = t; i < 32 * DN; i += 256) B3[i] = 0.f;

    // ---- v projections + weighted context ----
    for (int l = 0; l < LL; l++) {
        __syncthreads();                      // att visible; B2 readers done
        load_rows(bank, B2, rowid, LL * DN, (size_t)l * DN);
        gemm_tile(inw + 2 * DN * DN, B2, Wc, B2);
        // own-cell accumulate (gemm mapping); h == c>>5
#pragma unroll
        for (int i = 0; i < 8; i++) {
            int r = rg * 8 + i;
#pragma unroll
            for (int m = 0; m < 4; m++) {
                int c = cg * 128 + lane + (m << 5);
                B3[r * DN + c] += att[(r * NH + (c >> 5)) * LL + l] *
                                  (B2[r * DN + c] + sb[512 + c]);
            }
        }
    }

    // ---- out projection + residual + LN1 -> B1 ----
    gemm_tile(outw, B3, Wc, B2);
    __syncthreads();
    {
        int r = t >> 3, c0 = (t & 7) * 4;
        float4 vv[8]; float s1 = 0.f, s2 = 0.f;
#pragma unroll
        for (int j = 0; j < 8; j++) {
            int c = c0 + j * 32;
            float4 a = *(const float4*)&B2[r * DN + c];
            float4 rr = *(const float4*)&xb[r * DN + c];
            float4 bb = *(const float4*)&sb[768 + c];
            float x0 = a.x + bb.x + rr.x, x1 = a.y + bb.y + rr.y;
            float x2 = a.z + bb.z + rr.z, x3 = a.w + bb.w + rr.w;
            vv[j] = make_float4(x0, x1, x2, x3);
            s1 += x0 + x1 + x2 + x3;
            s2 += x0 * x0 + x1 * x1 + x2 * x2 + x3 * x3;
        }
        s1 = segSum8(s1); s2 = segSum8(s2);
        float mu = s1 * (1.f / DN);
        float var = fmaxf(s2 * (1.f / DN) - mu * mu, 0.f);
        float rstd = rsqrtf(var + 1e-5f);
#pragma unroll
        for (int j = 0; j < 8; j++) {
            int c = c0 + j * 32;
            float4 gg = *(const float4*)&sb[1536 + c];
            float4 bb = *(const float4*)&sb[1792 + c];
            float4 o;
            o.x = (vv[j].x - mu) * rstd * gg.x + bb.x;
            o.y = (vv[j].y - mu) * rstd * gg.y + bb.y;
            o.z = (vv[j].z - mu) * rstd * gg.z + bb.z;
            o.w = (vv[j].w - mu) * rstd * gg.w + bb.w;
            *(float4*)&B1[r * DN + c] = o;
        }
    }

    // ---- FFN ----
    gemm_tile(fc1w, B1, Wc, B2);
    // relu + bias, own cells
#pragma unroll
    for (int i = 0; i < 8; i++) {
        int r = rg * 8 + i;
#pragma unroll
        for (int m = 0; m < 4; m++) {
            int c = cg * 128 + lane + (m << 5);
            B2[r * DN + c] = fmaxf(B2[r * DN + c] + sb[1024 + c], 0.f);
        }
    }
    gemm_tile(fc2w, B2, Wc, B3);
    __syncthreads();

    // ---- residual + LN2 -> scatter to gmem ----
    {
        int r = t >> 3, c0 = (t & 7) * 4;
        float4 vv[8]; float s1 = 0.f, s2 = 0.f;
#pragma unroll
        for (int j = 0; j < 8; j++) {
            int c = c0 + j * 32;
            float4 a = *(const float4*)&B3[r * DN + c];
            float4 rr = *(const float4*)&B1[r * DN + c];
            float4 bb = *(const float4*)&sb[1280 + c];
            float x0 = a.x + bb.x + rr.x, x1 = a.y + bb.y + rr.y;
            float x2 = a.z + bb.z + rr.z, x3 = a.w + bb.w + rr.w;
            vv[j] = make_float4(x0, x1, x2, x3);
            s1 += x0 + x1 + x2 + x3;
            s2 += x0 * x0 + x1 * x1 + x2 * x2 + x3 * x3;
        }
        s1 = segSum8(s1); s2 = segSum8(s2);
        float mu = s1 * (1.f / DN);
        float var = fmaxf(s2 * (1.f / DN) - mu * mu, 0.f);
        float rstd = rsqrtf(var + 1e-5f);
        if (r < nrows) {
            size_t row = (size_t)rowid[r];
#pragma unroll
            for (int j = 0; j < 8; j++) {
                int c = c0 + j * 32;
                float4 gg = *(const float4*)&sb[2048 + c];
                float4 bb = *(const float4*)&sb[2304 + c];
                float4 o;
                o.x = (vv[j].x - mu) * rstd * gg.x + bb.x;
                o.y = (vv[j].y - mu) * rstd * gg.y + bb.y;
                o.z = (vv[j].z - mu) * rstd * gg.z + bb.z;
                o.w = (vv[j].w - mu) * rstd * gg.w + bb.w;
                *(float4*)&out[row * DN + c] = o;
            }
        }
    }
}

// ---------------- kernel C: bank shift/copy ----------------
__global__ __launch_bounds__(256) void kC(const float* __restrict__ scores,
                                          const float* __restrict__ bank,
                                          float* __restrict__ out, int n) {
    int w = threadIdx.x >> 5, lane = threadIdx.x & 31;
    int row = blockIdx.x * 8 + w;
    if (row >= n) return;
    bool saved = scores[row] > 0.f;
    const float4* b = (const float4*)(bank + (size_t)row * (LL * DN));
    float4* ob = (float4*)(out + (size_t)n * DN + (size_t)row * (LL * DN));
#pragma unroll
    for (int l = 0; l < LL; l++) {
        int src = saved ? l + 1 : l;
        if (src < LL) {
            ob[l * 64 + lane]      = b[src * 64 + lane];
            ob[l * 64 + lane + 32] = b[src * 64 + lane + 32];
        }
    }
}

// ---------------- kernel D: save_proj for saved rows -> bank slot L-1 -------
#define KD_XS_F 17408
#define KD_RID_F (17408 + 8192)
#define KD_SMEM ((17408 + 8192 + 32) * 4)
__global__ __launch_bounds__(256) void kD(const float* __restrict__ savew,
                                          const float* __restrict__ saveb,
                                          float* __restrict__ out, int n) {
    extern __shared__ float sm[];
    float* Wc = sm;
    float* xs = sm + KD_XS_F;
    int* rowid = (int*)(sm + KD_RID_F);

    const int cnt = g_cnts[1];
    const int tile = blockIdx.x;
    if (tile * 32 >= cnt) return;
    const int nrows = min(32, cnt - tile * 32);
    const int t = threadIdx.x, lane = t & 31, w = t >> 5;
    const int rg = w >> 1, cg = w & 1;
    if (t < 32) rowid[t] = g_slist[tile * 32 + min(t, nrows - 1)];
    __syncthreads();
    load_rows(out, xs, rowid, DN, 0);     // new_emb (final for all rows)
    gemm_tile(savew, xs, Wc, xs);         // in-place
    float* obank = out + (size_t)n * DN;
#pragma unroll
    for (int i = 0; i < 8; i++) {
        int r = rg * 8 + i;
        if (r < nrows) {
            size_t row = (size_t)rowid[r];
#pragma unroll
            for (int m = 0; m < 4; m++) {
                int c = cg * 128 + lane + (m << 5);
                obank[row * (LL * DN) + (LL - 1) * DN + c] =
                    xs[r * DN + c] + saveb[c];
            }
        }
    }
}

// ---------------- host launch ----------------
extern "C" void kernel_launch(void* const* d_in, const int* in_sizes, int n_in,
                              void* d_out, int out_size) {
    const float* emb    = (const float*)d_in[0];
    const float* scores = (const float*)d_in[1];
    const float* bank   = (const float*)d_in[2];
    const int*   maskg  = (const int*)d_in[3];
    const float* savew = (const float*)d_in[4];
    const float* saveb = (const float*)d_in[5];
    const float* inw   = (const float*)d_in[6];
    const float* inb   = (const float*)d_in[7];
    const float* outw  = (const float*)d_in[8];
    const float* outb  = (const float*)d_in[9];
    const float* fc1w  = (const float*)d_in[10];
    const float* fc1b  = (const float*)d_in[11];
    const float* fc2w  = (const float*)d_in[12];
    const float* fc2b  = (const float*)d_in[13];
    const float* g1    = (const float*)d_in[14];
    const float* b1    = (const float*)d_in[15];
    const float* g2    = (const float*)d_in[16];
    const float* b2    = (const float*)d_in[17];
    float* out = (float*)d_out;

    int n = in_sizes[1];   // scores length == N

    void* cntaddr = nullptr;
    cudaGetSymbolAddress(&cntaddr, g_cnts);
    cudaMemsetAsync(cntaddr, 0, 2 * sizeof(int));

    cudaFuncSetAttribute(kB, cudaFuncAttributeMaxDynamicSharedMemorySize, KB_SMEM);
    cudaFuncSetAttribute(kD, cudaFuncAttributeMaxDynamicSharedMemorySize, KD_SMEM);

    kA<<<(n + 7) / 8, 256>>>(emb, scores, maskg, out, n);
    kB<<<(n + 31) / 32, 256, KB_SMEM>>>(emb, bank, maskg, inw, inb, outw, outb,
                                        fc1w, fc1b, fc2w, fc2b, g1, b1, g2, b2,
                                        out, n);
    kC<<<(n + 7) / 8, 256>>>(scores, bank, out, n);
    kD<<<(n + 31) / 32, 256, KD_SMEM>>>(savew, saveb, out, n);
}

// round 9
// speedup vs baseline: 1.2448x; 1.0012x over previous
#include <cuda_runtime.h>
#include <cuda_bf16.h>
#include <stdint.h>
#include <math.h>

#define DN 256      // dim
#define LL 4        // memory bank len
#define NH 8        // heads
#define HD 32       // head dim
#define NMAX 100000
#define WCP 68      // Wc row stride in words (68 mod 32 == 4 -> conflict-free LDS.128/STS.128)

// ---------------- device globals ----------------
__device__ int g_cnts[2];              // [0]=valid count, [1]=saved count
__device__ int g_vlist[NMAX];
__device__ int g_slist[NMAX];

// ---------------- helpers ----------------
__device__ __forceinline__ uint64_t ffma2(uint64_t a, uint64_t b, uint64_t c) {
    uint64_t d;
    asm("fma.rn.f32x2 %0, %1, %2, %3;" : "=l"(d) : "l"(a), "l"(b), "l"(c));
    return d;
}
__device__ __forceinline__ float red2(uint64_t v) {
    float lo = __uint_as_float((unsigned)(v & 0xffffffffull));
    float hi = __uint_as_float((unsigned)(v >> 32));
    return lo + hi;
}
__device__ __forceinline__ float segSum8(float x) {
#pragma unroll
    for (int o = 4; o > 0; o >>= 1) x += __shfl_xor_sync(0xffffffffu, x, o, 8);
    return x;
}

// Gather 32 rows of 256 floats into smem tile s[32][256].
__device__ __forceinline__ void load_rows(const float* __restrict__ g, float* s,
                                          const int* rowid, size_t rowStride,
                                          size_t rowOff) {
    int w = threadIdx.x >> 5, lane = threadIdx.x & 31;
#pragma unroll
    for (int i = 0; i < 4; i++) {
        int r = w * 4 + i;
        const float4* src = (const float4*)(g + (size_t)rowid[r] * rowStride + rowOff);
        float4* dst = (float4*)(s + r * DN);
        dst[lane]      = src[lane];
        dst[lane + 32] = src[lane + 32];
    }
}

// Y[32,256] = X[32,256] * W^T  (W row-major [256 out][256 in]).
// 256 threads. warp w: rg=w>>1 owns rows rg*8..+7, cg=w&1 owns cols cg*128+lane+32m.
// Packed-over-k fp32 (fma.rn.f32x2). Y may alias X (writes after tail barrier).
// Caller must __syncthreads() before any cross-thread read of Y.
__device__ __forceinline__ void gemm_tile(const float* __restrict__ Wg,
                                          const float* __restrict__ X,
                                          float* __restrict__ Wc,
                                          float* __restrict__ Y) {
    const int t = threadIdx.x, lane = t & 31, w = t >> 5;
    const int rg = w >> 1, cg = w & 1;
    const float* Xr = X + (rg * 8) * DN;

    uint64_t acc2[8][4];
#pragma unroll
    for (int i = 0; i < 8; i++)
#pragma unroll
        for (int m = 0; m < 4; m++) acc2[i][m] = 0ull;

#pragma unroll 1
    for (int kc = 0; kc < DN; kc += 64) {
        __syncthreads();                      // Wc free of previous readers
        {   // stage 256x64 W chunk, o-major stride WCP
            int ko = (lane & 15) * 4;
            int oo = (w << 5) + (lane >> 4);
#pragma unroll
            for (int i = 0; i < 16; i++) {
                int o = oo + i * 2;
                float4 v = *(const float4*)&Wg[o * DN + kc + ko];
                *(float4*)&Wc[o * WCP + ko] = v;
            }
        }
        __syncthreads();
#pragma unroll 2
        for (int kk = 0; kk < 64; kk += 4) {
            ulonglong2 wv0 = *(const ulonglong2*)&Wc[(cg * 128 + lane) * WCP + kk];
            ulonglong2 wv1 = *(const ulonglong2*)&Wc[(cg * 128 + lane + 32) * WCP + kk];
            ulonglong2 wv2 = *(const ulonglong2*)&Wc[(cg * 128 + lane + 64) * WCP + kk];
            ulonglong2 wv3 = *(const ulonglong2*)&Wc[(cg * 128 + lane + 96) * WCP + kk];
#pragma unroll
            for (int i = 0; i < 8; i++) {
                ulonglong2 xv = *(const ulonglong2*)&Xr[i * DN + kc + kk];
                acc2[i][0] = ffma2(xv.x, wv0.x, acc2[i][0]);
                acc2[i][1] = ffma2(xv.x, wv1.x, acc2[i][1]);
                acc2[i][2] = ffma2(xv.x, wv2.x, acc2[i][2]);
                acc2[i][3] = ffma2(xv.x, wv3.x, acc2[i][3]);
                acc2[i][0] = ffma2(xv.y, wv0.y, acc2[i][0]);
                acc2[i][1] = ffma2(xv.y, wv1.y, acc2[i][1]);
                acc2[i][2] = ffma2(xv.y, wv2.y, acc2[i][2]);
                acc2[i][3] = ffma2(xv.y, wv3.y, acc2[i][3]);
            }
        }
    }
    __syncthreads();                           // all X reads done; Y may alias X
#pragma unroll
    for (int i = 0; i < 8; i++)
#pragma unroll
        for (int m = 0; m < 4; m++)
            Y[(rg * 8 + i) * DN + cg * 128 + lane + (m << 5)] = red2(acc2[i][m]);
}

// ---------------- kernel A: flags, new_mask, invalid-row copy, compaction ---
__global__ __launch_bounds__(256) void kA(const float* __restrict__ emb,
                                          const float* __restrict__ scores,
                                          const int* __restrict__ maskg,
                                          float* __restrict__ out, int n) {
    int w = threadIdx.x >> 5, lane = threadIdx.x & 31;
    int row = blockIdx.x * 8 + w;
    if (row >= n) return;
    bool saved = scores[row] > 0.f;
    bool valid = (maskg[(size_t)row * LL + (LL - 1)] == 0);

    float* omask = out + (size_t)n * DN + (size_t)n * (LL * DN);
    if (lane < LL) {
        int cur = maskg[(size_t)row * LL + lane];
        int nm = saved ? ((lane < LL - 1) ? maskg[(size_t)row * LL + lane + 1] : 0)
                       : cur;
        omask[(size_t)row * LL + lane] = nm ? 1.f : 0.f;
    }
    if (lane == 0) {
        if (valid) { int i = atomicAdd(&g_cnts[0], 1); g_vlist[i] = row; }
        if (saved) { int i = atomicAdd(&g_cnts[1], 1); g_slist[i] = row; }
    }
    if (!valid) {
        const float4* s = (const float4*)(emb + (size_t)row * DN);
        float4* d = (float4*)(out + (size_t)row * DN);
        d[lane]      = s[lane];
        d[lane + 32] = s[lane + 32];
    }
}

// ---------------- kernel B: fused transformer over valid rows ---------------
// smem float offsets
#define WC_F  0
#define XB_F  17408
#define B1_F  25600
#define B2_F  33792
#define B3_F  41984
#define LG_F  50176
#define ATT_F 51200
#define SB_F  52224            /* 10 x 256 bias/gain vectors */
#define RID_F 54784
#define MSK_F 54816
#define KB_SMEM (54944 * 4)

__global__ __launch_bounds__(256, 1) void kB(
    const float* __restrict__ emb, const float* __restrict__ bank,
    const int* __restrict__ maskg,
    const float* __restrict__ inw, const float* __restrict__ inb,
    const float* __restrict__ outw, const float* __restrict__ outb,
    const float* __restrict__ fc1w, const float* __restrict__ fc1b,
    const float* __restrict__ fc2w, const float* __restrict__ fc2b,
    const float* __restrict__ g1, const float* __restrict__ b1,
    const float* __restrict__ g2, const float* __restrict__ b2,
    float* __restrict__ out, int n) {
    extern __shared__ float sm[];
    float* Wc = sm + WC_F;
    float* xb = sm + XB_F;
    float* B1 = sm + B1_F;
    float* B2 = sm + B2_F;
    float* B3 = sm + B3_F;
    float* lg = sm + LG_F;                 // [32][8][4]
    float* att = sm + ATT_F;               // [32][8][4]
    float* sb = sm + SB_F;
    int* rowid = (int*)(sm + RID_F);
    int* msk = (int*)(sm + MSK_F);

    const int cnt = g_cnts[0];
    const int tile = blockIdx.x;
    if (tile * 32 >= cnt) return;
    const int nrows = min(32, cnt - tile * 32);
    const int t = threadIdx.x, lane = t & 31, w = t >> 5;
    const int rg = w >> 1, cg = w & 1;

    if (t < 32) rowid[t] = g_vlist[tile * 32 + min(t, nrows - 1)];
    // preload biases/gains into smem
    sb[t]        = inb[t];
    sb[256 + t]  = inb[256 + t];
    sb[512 + t]  = inb[512 + t];
    sb[768 + t]  = outb[t];
    sb[1024 + t] = fc1b[t];
    sb[1280 + t] = fc2b[t];
    sb[1536 + t] = g1[t];
    sb[1792 + t] = b1[t];
    sb[2048 + t] = g2[t];
    sb[2304 + t] = b2[t];
    __syncthreads();
    if (t < 32 * LL) msk[t] = maskg[(size_t)rowid[t >> 2] * LL + (t & 3)];
    load_rows(emb, xb, rowid, DN, 0);

    // ---- q projection (raw; biases folded into logits) ----
    gemm_tile(inw, xb, Wc, B1);

    // ---- k projections + logits ----
    for (int l = 0; l < LL; l++) {
        __syncthreads();                       // B1/B2 readers done
        load_rows(bank, B2, rowid, LL * DN, (size_t)l * DN);
        gemm_tile(inw + DN * DN, B2, Wc, B2);  // in-place
        __syncthreads();
        {
            int r = t >> 3, h = t & 7;
            float s = 0.f;
#pragma unroll 8
            for (int d0 = 0; d0 < HD; d0++) {
                int d = (d0 + t) & 31;
                int col = h * HD + d;
                int idx = r * DN + col;
                s += (B1[idx] + sb[col]) * (B2[idx] + sb[256 + col]);
            }
            lg[(r * NH + h) * LL + l] = s;
        }
    }

    // ---- softmax over L (own cells; no sync needed vs logits) ----
    {
        int r = t >> 3, h = t & 7;
        const float sc = 0.17677669529663687f;     // 1/sqrt(32)
        float v[LL]; float mx = -1e30f;
#pragma unroll
        for (int l = 0; l < LL; l++) {
            float x = msk[r * LL + l] ? -1e9f : lg[(r * NH + h) * LL + l] * sc;
            v[l] = x; mx = fmaxf(mx, x);
        }
        float s = 0.f;
#pragma unroll
        for (int l = 0; l < LL; l++) { v[l] = expf(v[l] - mx); s += v[l]; }
        float inv = 1.f / s;
#pragma unroll
        for (int l = 0; l < LL; l++) att[(r * NH + h) * LL + l] = v[l] * inv;
    }
    // zero ctx accumulator
    for (int i = t; i < 32 * DN; i += 256) B3[i] = 0.f;

    // ---- v projections + weighted context ----
    for (int l = 0; l < LL; l++) {
        __syncthreads();                      // att visible; B2 readers done
        load_rows(bank, B2, rowid, LL * DN, (size_t)l * DN);
        gemm_tile(inw + 2 * DN * DN, B2, Wc, B2);
        // own-cell accumulate (gemm mapping); h == c>>5
#pragma unroll
        for (int i = 0; i < 8; i++) {
            int r = rg * 8 + i;
#pragma unroll
            for (int m = 0; m < 4; m++) {
                int c = cg * 128 + lane + (m << 5);
                B3[r * DN + c] += att[(r * NH + (c >> 5)) * LL + l] *
                                  (B2[r * DN + c] + sb[512 + c]);
            }
        }
    }

    // ---- out projection + residual + LN1 -> B1 ----
    gemm_tile(outw, B3, Wc, B2);
    __syncthreads();
    {
        int r = t >> 3, c0 = (t & 7) * 4;
        float4 vv[8]; float s1 = 0.f, s2 = 0.f;
#pragma unroll
        for (int j = 0; j < 8; j++) {
            int c = c0 + j * 32;
            float4 a = *(const float4*)&B2[r * DN + c];
            float4 rr = *(const float4*)&xb[r * DN + c];
            float4 bb = *(const float4*)&sb[768 + c];
            float x0 = a.x + bb.x + rr.x, x1 = a.y + bb.y + rr.y;
            float x2 = a.z + bb.z + rr.z, x3 = a.w + bb.w + rr.w;
            vv[j] = make_float4(x0, x1, x2, x3);
            s1 += x0 + x1 + x2 + x3;
            s2 += x0 * x0 + x1 * x1 + x2 * x2 + x3 * x3;
        }
        s1 = segSum8(s1); s2 = segSum8(s2);
        float mu = s1 * (1.f / DN);
        float var = fmaxf(s2 * (1.f / DN) - mu * mu, 0.f);
        float rstd = rsqrtf(var + 1e-5f);
#pragma unroll
        for (int j = 0; j < 8; j++) {
            int c = c0 + j * 32;
            float4 gg = *(const float4*)&sb[1536 + c];
            float4 bb = *(const float4*)&sb[1792 + c];
            float4 o;
            o.x = (vv[j].x - mu) * rstd * gg.x + bb.x;
            o.y = (vv[j].y - mu) * rstd * gg.y + bb.y;
            o.z = (vv[j].z - mu) * rstd * gg.z + bb.z;
            o.w = (vv[j].w - mu) * rstd * gg.w + bb.w;
            *(float4*)&B1[r * DN + c] = o;
        }
    }

    // ---- FFN ----
    gemm_tile(fc1w, B1, Wc, B2);
    // relu + bias, own cells
#pragma unroll
    for (int i = 0; i < 8; i++) {
        int r = rg * 8 + i;
#pragma unroll
        for (int m = 0; m < 4; m++) {
            int c = cg * 128 + lane + (m << 5);
            B2[r * DN + c] = fmaxf(B2[r * DN + c] + sb[1024 + c], 0.f);
        }
    }
    gemm_tile(fc2w, B2, Wc, B3);
    __syncthreads();

    // ---- residual + LN2 -> scatter to gmem ----
    {
        int r = t >> 3, c0 = (t & 7) * 4;
        float4 vv[8]; float s1 = 0.f, s2 = 0.f;
#pragma unroll
        for (int j = 0; j < 8; j++) {
            int c = c0 + j * 32;
            float4 a = *(const float4*)&B3[r * DN + c];
            float4 rr = *(const float4*)&B1[r * DN + c];
            float4 bb = *(const float4*)&sb[1280 + c];
            float x0 = a.x + bb.x + rr.x, x1 = a.y + bb.y + rr.y;
            float x2 = a.z + bb.z + rr.z, x3 = a.w + bb.w + rr.w;
            vv[j] = make_float4(x0, x1, x2, x3);
            s1 += x0 + x1 + x2 + x3;
            s2 += x0 * x0 + x1 * x1 + x2 * x2 + x3 * x3;
        }
        s1 = segSum8(s1); s2 = segSum8(s2);
        float mu = s1 * (1.f / DN);
        float var = fmaxf(s2 * (1.f / DN) - mu * mu, 0.f);
        float rstd = rsqrtf(var + 1e-5f);
        if (r < nrows) {
            size_t row = (size_t)rowid[r];
#pragma unroll
            for (int j = 0; j < 8; j++) {
                int c = c0 + j * 32;
                float4 gg = *(const float4*)&sb[2048 + c];
                float4 bb = *(const float4*)&sb[2304 + c];
                float4 o;
                o.x = (vv[j].x - mu) * rstd * gg.x + bb.x;
                o.y = (vv[j].y - mu) * rstd * gg.y + bb.y;
                o.z = (vv[j].z - mu) * rstd * gg.z + bb.z;
                o.w = (vv[j].w - mu) * rstd * gg.w + bb.w;
                *(float4*)&out[row * DN + c] = o;
            }
        }
    }
}

// ---------------- kernel C: bank shift/copy ----------------
__global__ __launch_bounds__(256) void kC(const float* __restrict__ scores,
                                          const float* __restrict__ bank,
                                          float* __restrict__ out, int n) {
    int w = threadIdx.x >> 5, lane = threadIdx.x & 31;
    int row = blockIdx.x * 8 + w;
    if (row >= n) return;
    bool saved = scores[row] > 0.f;
    const float4* b = (const float4*)(bank + (size_t)row * (LL * DN));
    float4* ob = (float4*)(out + (size_t)n * DN + (size_t)row * (LL * DN));
#pragma unroll
    for (int l = 0; l < LL; l++) {
        int src = saved ? l + 1 : l;
        if (src < LL) {
            ob[l * 64 + lane]      = b[src * 64 + lane];
            ob[l * 64 + lane + 32] = b[src * 64 + lane + 32];
        }
    }
}

// ---------------- kernel D: save_proj for saved rows -> bank slot L-1 -------
#define KD_XS_F 17408
#define KD_RID_F (17408 + 8192)
#define KD_SMEM ((17408 + 8192 + 32) * 4)
__global__ __launch_bounds__(256) void kD(const float* __restrict__ savew,
                                          const float* __restrict__ saveb,
                                          float* __restrict__ out, int n) {
    extern __shared__ float sm[];
    float* Wc = sm;
    float* xs = sm + KD_XS_F;
    int* rowid = (int*)(sm + KD_RID_F);

    const int cnt = g_cnts[1];
    const int tile = blockIdx.x;
    if (tile * 32 >= cnt) return;
    const int nrows = min(32, cnt - tile * 32);
    const int t = threadIdx.x, lane = t & 31, w = t >> 5;
    const int rg = w >> 1, cg = w & 1;
    if (t < 32) rowid[t] = g_slist[tile * 32 + min(t, nrows - 1)];
    __syncthreads();
    load_rows(out, xs, rowid, DN, 0);     // new_emb (final for all rows)
    gemm_tile(savew, xs, Wc, xs);         // in-place
    float* obank = out + (size_t)n * DN;
#pragma unroll
    for (int i = 0; i < 8; i++) {
        int r = rg * 8 + i;
        if (r < nrows) {
            size_t row = (size_t)rowid[r];
#pragma unroll
            for (int m = 0; m < 4; m++) {
                int c = cg * 128 + lane + (m << 5);
                obank[row * (LL * DN) + (LL - 1) * DN + c] =
                    xs[r * DN + c] + saveb[c];
            }
        }
    }
}

// ---------------- host launch ----------------
extern "C" void kernel_launch(void* const* d_in, const int* in_sizes, int n_in,
                              void* d_out, int out_size) {
    const float* emb    = (const float*)d_in[0];
    const float* scores = (const float*)d_in[1];
    const float* bank   = (const float*)d_in[2];
    const int*   maskg  = (const int*)d_in[3];
    const float* savew = (const float*)d_in[4];
    const float* saveb = (const float*)d_in[5];
    const float* inw   = (const float*)d_in[6];
    const float* inb   = (const float*)d_in[7];
    const float* outw  = (const float*)d_in[8];
    const float* outb  = (const float*)d_in[9];
    const float* fc1w  = (const float*)d_in[10];
    const float* fc1b  = (const float*)d_in[11];
    const float* fc2w  = (const float*)d_in[12];
    const float* fc2b  = (const float*)d_in[13];
    const float* g1    = (const float*)d_in[14];
    const float* b1    = (const float*)d_in[15];
    const float* g2    = (const float*)d_in[16];
    const float* b2    = (const float*)d_in[17];
    float* out = (float*)d_out;

    int n = in_sizes[1];   // scores length == N

    void* cntaddr = nullptr;
    cudaGetSymbolAddress(&cntaddr, g_cnts);
    cudaMemsetAsync(cntaddr, 0, 2 * sizeof(int));

    cudaFuncSetAttribute(kB, cudaFuncAttributeMaxDynamicSharedMemorySize, KB_SMEM);
    cudaFuncSetAttribute(kD, cudaFuncAttributeMaxDynamicSharedMemorySize, KD_SMEM);

    kA<<<(n + 7) / 8, 256>>>(emb, scores, maskg, out, n);
    kB<<<(n + 31) / 32, 256, KB_SMEM>>>(emb, bank, maskg, inw, inb, outw, outb,
                                        fc1w, fc1b, fc2w, fc2b, g1, b1, g2, b2,
                                        out, n);
    kC<<<(n + 7) / 8, 256>>>(scores, bank, out, n);
    kD<<<(n + 31) / 32, 256, KD_SMEM>>>(savew, saveb, out, n);
}

// round 14
// speedup vs baseline: 1.6038x; 1.2884x over previous
#include <cuda_runtime.h>
#include <stdint.h>
#include <math.h>

#define DN 256      // dim
#define LL 4        // memory bank len
#define NH 8        // heads
#define NMAX 100000
#define XST 260     // smem activation row stride (260 % 32 == 4 -> conflict-free ldmatrix)
#define WCP 68      // Wc row stride (68 % 32 == 4)

// ---------------- device globals ----------------
__device__ int g_cnts[2];
__device__ int g_vlist[NMAX];
__device__ int g_slist[NMAX];

// ---------------- low-level helpers ----------------
__device__ __forceinline__ uint32_t s2u(const void* p) {
    uint32_t a;
    asm("{ .reg .u64 t; cvta.to.shared.u64 t, %1; cvt.u32.u64 %0, t; }" : "=r"(a) : "l"(p));
    return a;
}
__device__ __forceinline__ uint32_t tf32r(float x) {
    uint32_t u; asm("cvt.rna.tf32.f32 %0, %1;" : "=r"(u) : "f"(x)); return u;
}
__device__ __forceinline__ void sts128(uint32_t a, uint32_t x, uint32_t y, uint32_t z, uint32_t w) {
    asm volatile("st.shared.v4.b32 [%0], {%1,%2,%3,%4};" :: "r"(a), "r"(x), "r"(y), "r"(z), "r"(w));
}
__device__ __forceinline__ void ldsm4(uint32_t* r, uint32_t a) {
    asm volatile("ldmatrix.sync.aligned.m8n8.x4.shared.b16 {%0,%1,%2,%3}, [%4];"
                 : "=r"(r[0]), "=r"(r[1]), "=r"(r[2]), "=r"(r[3]) : "r"(a));
}
__device__ __forceinline__ void mma8(float* d, const uint32_t* a, const uint32_t* b) {
    asm volatile("mma.sync.aligned.m16n8k8.row.col.f32.tf32.tf32.f32 "
                 "{%0,%1,%2,%3}, {%4,%5,%6,%7}, {%8,%9}, {%0,%1,%2,%3};"
                 : "+f"(d[0]), "+f"(d[1]), "+f"(d[2]), "+f"(d[3])
                 : "r"(a[0]), "r"(a[1]), "r"(a[2]), "r"(a[3]), "r"(b[0]), "r"(b[1]));
}
__device__ __forceinline__ float segSum8(float x) {
#pragma unroll
    for (int o = 4; o > 0; o >>= 1) x += __shfl_xor_sync(0xffffffffu, x, o, 8);
    return x;
}

// Gather 32 rows of 256 floats into smem tile s[32][XST].
__device__ __forceinline__ void load_rows(const float* __restrict__ g, float* s,
                                          const int* rowid, size_t gstride, size_t goff) {
    int w = threadIdx.x >> 5, lane = threadIdx.x & 31;
#pragma unroll
    for (int i = 0; i < 4; i++) {
        int r = w * 4 + i;
        const float4* src = (const float4*)(g + (size_t)rowid[r] * gstride + goff);
        float4* dst = (float4*)(s + r * XST);
        dst[lane]      = src[lane];
        dst[lane + 32] = src[lane + 32];
    }
}

// Y[32,256] = X[32,256](stride XST) * W^T (W row-major [256][256] gmem, rna->tf32 staged).
// Warp w owns all 32 rows x cols [w*32, w*32+32). tf32 tensor-core mma.
// Own-cell mapping: rb{0,1}, j{0..3}, s{0,1}, d{0,1}:
//   r = rb*16 + (lane>>2) + s*8 ; c = w*32 + j*8 + (lane&3)*2 + d ; val acc[rb][j][s*2+d]
// Y may alias X. Caller must __syncthreads() before cross-thread reads of Y.
__device__ __forceinline__ void gemm_tile(const float* __restrict__ Wg,
                                          const float* __restrict__ X,
                                          float* __restrict__ Wc,
                                          float* __restrict__ Y) {
    const int t = threadIdx.x, lane = t & 31, w = t >> 5;
    const uint32_t sX = s2u(X), sW = s2u(Wc);
    // ldmatrix per-thread row addresses
    const uint32_t aRow = ((lane >> 3) & 1) * 8 + (lane & 7);
    const uint32_t aCol = (lane >> 4) * 4;
    const uint32_t bRow = (lane >> 4) * 8 + (lane & 7);
    const uint32_t bCol = ((lane >> 3) & 1) * 4;
    const uint32_t aB0 = sX + (aRow * XST + aCol) * 4;
    const uint32_t aB1 = sX + ((16 + aRow) * XST + aCol) * 4;
    const uint32_t bB0 = sW + (((uint32_t)w * 32 + bRow) * WCP + bCol) * 4;
    const uint32_t bB1 = sW + (((uint32_t)w * 32 + 16 + bRow) * WCP + bCol) * 4;

    float acc[2][4][4];
#pragma unroll
    for (int i = 0; i < 2; i++)
#pragma unroll
        for (int j = 0; j < 4; j++)
#pragma unroll
            for (int q = 0; q < 4; q++) acc[i][j][q] = 0.f;

#pragma unroll 1
    for (int kc = 0; kc < DN; kc += 64) {
        __syncthreads();                       // Wc free of previous readers
        {   // stage 256x64 W chunk (rna->tf32), o-major stride WCP
            const int ko = (lane & 15) * 4;
            const int oo = (w << 5) + (lane >> 4);
#pragma unroll
            for (int i = 0; i < 16; i++) {
                int o = oo + i * 2;
                float4 v = *(const float4*)&Wg[o * DN + kc + ko];
                sts128(sW + (uint32_t)(o * WCP + ko) * 4,
                       tf32r(v.x), tf32r(v.y), tf32r(v.z), tf32r(v.w));
            }
        }
        __syncthreads();
#pragma unroll
        for (int ks = 0; ks < 64; ks += 8) {
            uint32_t a0[4], a1[4], b0[4], b1[4];
            ldsm4(a0, aB0 + (uint32_t)(kc + ks) * 4);
            ldsm4(a1, aB1 + (uint32_t)(kc + ks) * 4);
            ldsm4(b0, bB0 + (uint32_t)ks * 4);
            ldsm4(b1, bB1 + (uint32_t)ks * 4);
            mma8(acc[0][0], a0, b0);     mma8(acc[0][1], a0, b0 + 2);
            mma8(acc[0][2], a0, b1);     mma8(acc[0][3], a0, b1 + 2);
            mma8(acc[1][0], a1, b0);     mma8(acc[1][1], a1, b0 + 2);
            mma8(acc[1][2], a1, b1);     mma8(acc[1][3], a1, b1 + 2);
        }
    }
    __syncthreads();                           // all X reads done; Y may alias X
#pragma unroll
    for (int rb = 0; rb < 2; rb++)
#pragma unroll
        for (int j = 0; j < 4; j++) {
            int r0 = rb * 16 + (lane >> 2);
            int c = w * 32 + j * 8 + (lane & 3) * 2;
            *(float2*)&Y[r0 * XST + c]       = make_float2(acc[rb][j][0], acc[rb][j][1]);
            *(float2*)&Y[(r0 + 8) * XST + c] = make_float2(acc[rb][j][2], acc[rb][j][3]);
        }
}

// ---------------- kernel A: flags, new_mask, invalid copy, compaction ----------------
__global__ __launch_bounds__(256) void kA(const float* __restrict__ emb,
                                          const float* __restrict__ scores,
                                          const int* __restrict__ maskg,
                                          float* __restrict__ out, int n) {
    int w = threadIdx.x >> 5, lane = threadIdx.x & 31;
    int row = blockIdx.x * 8 + w;
    if (row >= n) return;
    bool saved = scores[row] > 0.f;
    bool valid = (maskg[(size_t)row * LL + (LL - 1)] == 0);
    float* omask = out + (size_t)n * DN + (size_t)n * (LL * DN);
    if (lane < LL) {
        int cur = maskg[(size_t)row * LL + lane];
        int nm = saved ? ((lane < LL - 1) ? maskg[(size_t)row * LL + lane + 1] : 0) : cur;
        omask[(size_t)row * LL + lane] = nm ? 1.f : 0.f;
    }
    if (lane == 0) {
        if (valid) { int i = atomicAdd(&g_cnts[0], 1); g_vlist[i] = row; }
        if (saved) { int i = atomicAdd(&g_cnts[1], 1); g_slist[i] = row; }
    }
    if (!valid) {
        const float4* s = (const float4*)(emb + (size_t)row * DN);
        float4* d = (float4*)(out + (size_t)row * DN);
        d[lane] = s[lane]; d[lane + 32] = s[lane + 32];
    }
}

// ---------------- kernel B: fused transformer over valid rows ----------------
// smem float offsets
#define WC_F  0
#define XB_F  17408
#define B1_F  25728
#define B2_F  34048
#define B3_F  42368
#define LG_F  50688
#define ATT_F 51712
#define SB_F  52736
#define RID_F 55296
#define MSK_F 55328
#define KB_SMEM (55456 * 4)

__global__ __launch_bounds__(256, 1) void kB(
    const float* __restrict__ emb, const float* __restrict__ bank,
    const int* __restrict__ maskg,
    const float* __restrict__ inw, const float* __restrict__ inb,
    const float* __restrict__ outw, const float* __restrict__ outb,
    const float* __restrict__ fc1w, const float* __restrict__ fc1b,
    const float* __restrict__ fc2w, const float* __restrict__ fc2b,
    const float* __restrict__ g1, const float* __restrict__ b1,
    const float* __restrict__ g2, const float* __restrict__ b2,
    float* __restrict__ out, int n) {
    extern __shared__ float sm[];
    float* Wc = sm + WC_F;
    float* xb = sm + XB_F;
    float* B1 = sm + B1_F;
    float* B2 = sm + B2_F;
    float* B3 = sm + B3_F;
    float* lg = sm + LG_F;
    float* att = sm + ATT_F;
    float* sb = sm + SB_F;
    int* rowid = (int*)(sm + RID_F);
    int* msk = (int*)(sm + MSK_F);

    const int cnt = g_cnts[0];
    const int tile = blockIdx.x;
    if (tile * 32 >= cnt) return;
    const int nrows = min(32, cnt - tile * 32);
    const int t = threadIdx.x, lane = t & 31, w = t >> 5;

    if (t < 32) rowid[t] = g_vlist[tile * 32 + min(t, nrows - 1)];
    sb[t]        = inb[t];
    sb[256 + t]  = inb[256 + t];
    sb[512 + t]  = inb[512 + t];
    sb[768 + t]  = outb[t];
    sb[1024 + t] = fc1b[t];
    sb[1280 + t] = fc2b[t];
    sb[1536 + t] = g1[t];
    sb[1792 + t] = b1[t];
    sb[2048 + t] = g2[t];
    sb[2304 + t] = b2[t];
    __syncthreads();
    if (t < 32 * LL) msk[t] = maskg[(size_t)rowid[t >> 2] * LL + (t & 3)];
    load_rows(emb, xb, rowid, DN, 0);

    // ---- q projection (raw; q/k biases folded into logits) ----
    gemm_tile(inw, xb, Wc, B1);

    // ---- k projections + logits ----
    for (int l = 0; l < LL; l++) {
        __syncthreads();                       // B1/B2 readers done
        load_rows(bank, B2, rowid, LL * DN, (size_t)l * DN);
        gemm_tile(inw + DN * DN, B2, Wc, B2);  // in-place
        __syncthreads();
        {
            int r = t >> 3, h = t & 7;
            float s = 0.f;
#pragma unroll 8
            for (int d0 = 0; d0 < 32; d0++) {
                int d = (d0 + t) & 31;
                int col = h * 32 + d;
                int idx = r * XST + col;
                s += (B1[idx] + sb[col]) * (B2[idx] + sb[256 + col]);
            }
            lg[(r * NH + h) * LL + l] = s;
        }
    }

    // ---- softmax over L ----
    {
        int r = t >> 3, h = t & 7;
        const float sc = 0.17677669529663687f;
        float v[LL]; float mx = -1e30f;
#pragma unroll
        for (int l = 0; l < LL; l++) {
            float x = msk[r * LL + l] ? -1e9f : lg[(r * NH + h) * LL + l] * sc;
            v[l] = x; mx = fmaxf(mx, x);
        }
        float s = 0.f;
#pragma unroll
        for (int l = 0; l < LL; l++) { v[l] = expf(v[l] - mx); s += v[l]; }
        float inv = 1.f / s;
#pragma unroll
        for (int l = 0; l < LL; l++) att[(r * NH + h) * LL + l] = v[l] * inv;
    }
    for (int i = t; i < 32 * XST; i += 256) B3[i] = 0.f;

    // ---- v projections + weighted context (head h == warp w since c>>5 == w) ----
    for (int l = 0; l < LL; l++) {
        __syncthreads();                      // att + B3-zero visible; B2 readers done
        load_rows(bank, B2, rowid, LL * DN, (size_t)l * DN);
        gemm_tile(inw + 2 * DN * DN, B2, Wc, B2);
#pragma unroll
        for (int rb = 0; rb < 2; rb++)
#pragma unroll
            for (int j = 0; j < 4; j++)
#pragma unroll
                for (int q = 0; q < 4; q++) {
                    int r = rb * 16 + (lane >> 2) + (q >> 1) * 8;
                    int c = w * 32 + j * 8 + (lane & 3) * 2 + (q & 1);
                    B3[r * XST + c] += att[(r * NH + w) * LL + l] *
                                       (B2[r * XST + c] + sb[512 + c]);
                }
    }

    // ---- out projection + residual + LN1 -> B1 ----
    gemm_tile(outw, B3, Wc, B2);
    __syncthreads();
    {
        int r = t >> 3, c0 = (t & 7) * 4;
        float4 vv[8]; float s1 = 0.f, s2 = 0.f;
#pragma unroll
        for (int j = 0; j < 8; j++) {
            int c = c0 + j * 32;
            float4 a = *(const float4*)&B2[r * XST + c];
            float4 rr = *(const float4*)&xb[r * XST + c];
            float4 bb = *(const float4*)&sb[768 + c];
            float x0 = a.x + bb.x + rr.x, x1 = a.y + bb.y + rr.y;
            float x2 = a.z + bb.z + rr.z, x3 = a.w + bb.w + rr.w;
            vv[j] = make_float4(x0, x1, x2, x3);
            s1 += x0 + x1 + x2 + x3;
            s2 += x0 * x0 + x1 * x1 + x2 * x2 + x3 * x3;
        }
        s1 = segSum8(s1); s2 = segSum8(s2);
        float mu = s1 * (1.f / DN);
        float rstd = rsqrtf(fmaxf(s2 * (1.f / DN) - mu * mu, 0.f) + 1e-5f);
#pragma unroll
        for (int j = 0; j < 8; j++) {
            int c = c0 + j * 32;
            float4 gg = *(const float4*)&sb[1536 + c];
            float4 bb = *(const float4*)&sb[1792 + c];
            float4 o;
            o.x = (vv[j].x - mu) * rstd * gg.x + bb.x;
            o.y = (vv[j].y - mu) * rstd * gg.y + bb.y;
            o.z = (vv[j].z - mu) * rstd * gg.z + bb.z;
            o.w = (vv[j].w - mu) * rstd * gg.w + bb.w;
            *(float4*)&B1[r * XST + c] = o;
        }
    }

    // ---- FFN ----
    gemm_tile(fc1w, B1, Wc, B2);
#pragma unroll
    for (int rb = 0; rb < 2; rb++)
#pragma unroll
        for (int j = 0; j < 4; j++)
#pragma unroll
            for (int q = 0; q < 4; q++) {
                int r = rb * 16 + (lane >> 2) + (q >> 1) * 8;
                int c = w * 32 + j * 8 + (lane & 3) * 2 + (q & 1);
                B2[r * XST + c] = fmaxf(B2[r * XST + c] + sb[1024 + c], 0.f);
            }
    gemm_tile(fc2w, B2, Wc, B3);
    __syncthreads();

    // ---- residual + LN2 -> scatter ----
    {
        int r = t >> 3, c0 = (t & 7) * 4;
        float4 vv[8]; float s1 = 0.f, s2 = 0.f;
#pragma unroll
        for (int j = 0; j < 8; j++) {
            int c = c0 + j * 32;
            float4 a = *(const float4*)&B3[r * XST + c];
            float4 rr = *(const float4*)&B1[r * XST + c];
            float4 bb = *(const float4*)&sb[1280 + c];
            float x0 = a.x + bb.x + rr.x, x1 = a.y + bb.y + rr.y;
            float x2 = a.z + bb.z + rr.z, x3 = a.w + bb.w + rr.w;
            vv[j] = make_float4(x0, x1, x2, x3);
            s1 += x0 + x1 + x2 + x3;
            s2 += x0 * x0 + x1 * x1 + x2 * x2 + x3 * x3;
        }
        s1 = segSum8(s1); s2 = segSum8(s2);
        float mu = s1 * (1.f / DN);
        float rstd = rsqrtf(fmaxf(s2 * (1.f / DN) - mu * mu, 0.f) + 1e-5f);
        if (r < nrows) {
            size_t row = (size_t)rowid[r];
#pragma unroll
            for (int j = 0; j < 8; j++) {
                int c = c0 + j * 32;
                float4 gg = *(const float4*)&sb[2048 + c];
                float4 bb = *(const float4*)&sb[2304 + c];
                float4 o;
                o.x = (vv[j].x - mu) * rstd * gg.x + bb.x;
                o.y = (vv[j].y - mu) * rstd * gg.y + bb.y;
                o.z = (vv[j].z - mu) * rstd * gg.z + bb.z;
                o.w = (vv[j].w - mu) * rstd * gg.w + bb.w;
                *(float4*)&out[row * DN + c] = o;
            }
        }
    }
}

// ---------------- kernel C: bank shift/copy ----------------
__global__ __launch_bounds__(256) void kC(const float* __restrict__ scores,
                                          const float* __restrict__ bank,
                                          float* __restrict__ out, int n) {
    int w = threadIdx.x >> 5, lane = threadIdx.x & 31;
    int row = blockIdx.x * 8 + w;
    if (row >= n) return;
    bool saved = scores[row] > 0.f;
    const float4* b = (const float4*)(bank + (size_t)row * (LL * DN));
    float4* ob = (float4*)(out + (size_t)n * DN + (size_t)row * (LL * DN));
#pragma unroll
    for (int l = 0; l < LL; l++) {
        int src = saved ? l + 1 : l;
        if (src < LL) {
            ob[l * 64 + lane]      = b[src * 64 + lane];
            ob[l * 64 + lane + 32] = b[src * 64 + lane + 32];
        }
    }
}

// ---------------- kernel D: save_proj for saved rows -> bank slot L-1 ----------------
#define KD_XS_F 17408
#define KD_RID_F (17408 + 32 * XST)
#define KD_SMEM ((17408 + 32 * XST + 32) * 4)
__global__ __launch_bounds__(256) void kD(const float* __restrict__ savew,
                                          const float* __restrict__ saveb,
                                          float* __restrict__ out, int n) {
    extern __shared__ float sm[];
    float* Wc = sm;
    float* xs = sm + KD_XS_F;
    int* rowid = (int*)(sm + KD_RID_F);

    const int cnt = g_cnts[1];
    const int tile = blockIdx.x;
    if (tile * 32 >= cnt) return;
    const int nrows = min(32, cnt - tile * 32);
    const int t = threadIdx.x, lane = t & 31, w = t >> 5;
    if (t < 32) rowid[t] = g_slist[tile * 32 + min(t, nrows - 1)];
    __syncthreads();
    load_rows(out, xs, rowid, DN, 0);     // new_emb (final for all rows)
    gemm_tile(savew, xs, Wc, xs);         // in-place
    __syncthreads();
    float* obank = out + (size_t)n * DN;
#pragma unroll
    for (int i = 0; i < 4; i++) {
        int r = w * 4 + i;
        if (r < nrows) {
            size_t row = (size_t)rowid[r];
            float* orow = obank + row * (LL * DN) + (LL - 1) * DN;
#pragma unroll
            for (int v = 0; v < 2; v++) {
                int c = (lane + v * 32) * 4;
                float4 x = *(const float4*)&xs[r * XST + c];
                float4 bb = *(const float4*)&saveb[c];
                *(float4*)&orow[c] = make_float4(x.x + bb.x, x.y + bb.y,
                                                 x.z + bb.z, x.w + bb.w);
            }
        }
    }
}

// ---------------- host launch ----------------
extern "C" void kernel_launch(void* const* d_in, const int* in_sizes, int n_in,
                              void* d_out, int out_size) {
    const float* emb    = (const float*)d_in[0];
    const float* scores = (const float*)d_in[1];
    const float* bank   = (const float*)d_in[2];
    const int*   maskg  = (const int*)d_in[3];
    const float* savew = (const float*)d_in[4];
    const float* saveb = (const float*)d_in[5];
    const float* inw   = (const float*)d_in[6];
    const float* inb   = (const float*)d_in[7];
    const float* outw  = (const float*)d_in[8];
    const float* outb  = (const float*)d_in[9];
    const float* fc1w  = (const float*)d_in[10];
    const float* fc1b  = (const float*)d_in[11];
    const float* fc2w  = (const float*)d_in[12];
    const float* fc2b  = (const float*)d_in[13];
    const float* g1    = (const float*)d_in[14];
    const float* b1    = (const float*)d_in[15];
    const float* g2    = (const float*)d_in[16];
    const float* b2    = (const float*)d_in[17];
    float* out = (float*)d_out;
    int n = in_sizes[1];

    void* cntaddr = nullptr;
    cudaGetSymbolAddress(&cntaddr, g_cnts);
    cudaMemsetAsync(cntaddr, 0, 2 * sizeof(int));

    cudaFuncSetAttribute(kB, cudaFuncAttributeMaxDynamicSharedMemorySize, KB_SMEM);
    cudaFuncSetAttribute(kD, cudaFuncAttributeMaxDynamicSharedMemorySize, KD_SMEM);

    kA<<<(n + 7) / 8, 256>>>(emb, scores, maskg, out, n);
    kB<<<(n + 31) / 32, 256, KB_SMEM>>>(emb, bank, maskg, inw, inb, outw, outb,
                                        fc1w, fc1b, fc2w, fc2b, g1, b1, g2, b2,
                                        out, n);
    kC<<<(n + 7) / 8, 256>>>(scores, bank, out, n);
    kD<<<(n + 31) / 32, 256, KD_SMEM>>>(savew, saveb, out, n);
}

// round 15
// speedup vs baseline: 2.3591x; 1.4710x over previous
#include <cuda_runtime.h>
#include <stdint.h>
#include <math.h>

#define DN 256      // dim
#define LL 4        // memory bank len
#define NH 8        // heads
#define NMAX 100000
#define XST 260     // smem activation row stride (mod 32 == 4 -> conflict-free ldmatrix)
#define WST 36      // Wc row stride (mod 32 == 4)

// ---------------- device globals ----------------
__device__ int g_cnts[2];
__device__ int g_vlist[NMAX];
__device__ int g_slist[NMAX];

// ---------------- low-level helpers ----------------
__device__ __forceinline__ uint32_t s2u(const void* p) {
    uint32_t a;
    asm("{ .reg .u64 t; cvta.to.shared.u64 t, %1; cvt.u32.u64 %0, t; }" : "=r"(a) : "l"(p));
    return a;
}
__device__ __forceinline__ uint32_t tf32r(float x) {
    uint32_t u; asm("cvt.rna.tf32.f32 %0, %1;" : "=r"(u) : "f"(x)); return u;
}
__device__ __forceinline__ void sts128(uint32_t a, uint32_t x, uint32_t y, uint32_t z, uint32_t w) {
    asm volatile("st.shared.v4.b32 [%0], {%1,%2,%3,%4};" :: "r"(a), "r"(x), "r"(y), "r"(z), "r"(w));
}
__device__ __forceinline__ void ldsm4(uint32_t* r, uint32_t a) {
    asm volatile("ldmatrix.sync.aligned.m8n8.x4.shared.b16 {%0,%1,%2,%3}, [%4];"
                 : "=r"(r[0]), "=r"(r[1]), "=r"(r[2]), "=r"(r[3]) : "r"(a));
}
__device__ __forceinline__ void mma8(float* d, const uint32_t* a, const uint32_t* b) {
    asm volatile("mma.sync.aligned.m16n8k8.row.col.f32.tf32.tf32.f32 "
                 "{%0,%1,%2,%3}, {%4,%5,%6,%7}, {%8,%9}, {%0,%1,%2,%3};"
                 : "+f"(d[0]), "+f"(d[1]), "+f"(d[2]), "+f"(d[3])
                 : "r"(a[0]), "r"(a[1]), "r"(a[2]), "r"(a[3]), "r"(b[0]), "r"(b[1]));
}
__device__ __forceinline__ float segSum8(float x) {
#pragma unroll
    for (int o = 4; o > 0; o >>= 1) x += __shfl_xor_sync(0xffffffffu, x, o, 8);
    return x;
}

// Gather 32 rows of 256 floats into smem tile s[32][XST].
__device__ __forceinline__ void load_rows(const float* __restrict__ g, float* s,
                                          const int* rowid, size_t gstride, size_t goff) {
    int w = threadIdx.x >> 5, lane = threadIdx.x & 31;
#pragma unroll
    for (int i = 0; i < 4; i++) {
        int r = w * 4 + i;
        const float4* src = (const float4*)(g + (size_t)rowid[r] * gstride + goff);
        float4* dst = (float4*)(s + r * XST);
        dst[lane]      = src[lane];
        dst[lane + 32] = src[lane + 32];
    }
}

// Stage all 4 bank slots for 32 tracks as 128 rows: row = l*32 + r.
__device__ __forceinline__ void stage_bank(const float* __restrict__ bank,
                                           float* __restrict__ AB, const int* rowid) {
    int t = threadIdx.x;
#pragma unroll
    for (int j = 0; j < 32; j++) {
        int f = t + j * 256;                 // 0..8191 float4s
        int row = f >> 6, v = f & 63;
        int l = row >> 5, r = row & 31;
        const float4* src = (const float4*)(bank + (size_t)rowid[r] * (LL * DN) + (size_t)l * DN);
        *(float4*)&AB[row * XST + v * 4] = src[v];
    }
}

// Y[RB*16,256] = X[RB*16,256](stride XST) @ W^T  (W row-major [256][256] gmem, rna->tf32).
// 256 threads; warp w owns cols [w*32, w*32+32) over all rows.
// Own-cell map: rb, j, q: r = rb*16 + (lane>>2) + (q>>1)*8 ; c = w*32 + j*8 + (lane&3)*2 + (q&1).
// Y may alias X (stores after tail barrier). Caller syncs before cross-thread reads of Y.
template<int RB>
__device__ __forceinline__ void gemmT(const float* __restrict__ Wg,
                                      const float* __restrict__ X,
                                      float* __restrict__ Wc,
                                      float* __restrict__ Y) {
    const int t = threadIdx.x, lane = t & 31, w = t >> 5;
    const uint32_t sX = s2u(X), sW = s2u(Wc);
    const uint32_t aRow = ((lane >> 3) & 1) * 8 + (lane & 7);
    const uint32_t aCol = (lane >> 4) * 4;
    const uint32_t bRow = (lane >> 4) * 8 + (lane & 7);
    const uint32_t bCol = ((lane >> 3) & 1) * 4;
    const uint32_t bB0 = sW + (((uint32_t)w * 32 + bRow) * WST + bCol) * 4;
    const uint32_t bB1 = sW + (((uint32_t)w * 32 + 16 + bRow) * WST + bCol) * 4;

    float acc[RB][4][4];
#pragma unroll
    for (int rb = 0; rb < RB; rb++)
#pragma unroll
        for (int j = 0; j < 4; j++)
#pragma unroll
            for (int q = 0; q < 4; q++) acc[rb][j][q] = 0.f;

    const int so = t >> 3, sk = (t & 7) * 4;
#pragma unroll 1
    for (int kc = 0; kc < DN; kc += 32) {
        __syncthreads();                       // Wc free of previous readers
#pragma unroll
        for (int p = 0; p < 8; p++) {          // stage 256x32 W chunk (rna->tf32)
            int o = so + p * 32;
            float4 v = *(const float4*)&Wg[o * DN + kc + sk];
            sts128(sW + (uint32_t)(o * WST + sk) * 4,
                   tf32r(v.x), tf32r(v.y), tf32r(v.z), tf32r(v.w));
        }
        __syncthreads();
#pragma unroll
        for (int ks = 0; ks < 32; ks += 8) {
            uint32_t b0[4], b1[4];
            ldsm4(b0, bB0 + (uint32_t)ks * 4);
            ldsm4(b1, bB1 + (uint32_t)ks * 4);
#pragma unroll
            for (int rb = 0; rb < RB; rb++) {
                uint32_t a[4];
                ldsm4(a, sX + (uint32_t)((rb * 16 + aRow) * XST + aCol + kc + ks) * 4);
                mma8(acc[rb][0], a, b0);   mma8(acc[rb][1], a, b0 + 2);
                mma8(acc[rb][2], a, b1);   mma8(acc[rb][3], a, b1 + 2);
            }
        }
    }
    __syncthreads();                           // all X reads done; Y may alias X
#pragma unroll
    for (int rb = 0; rb < RB; rb++)
#pragma unroll
        for (int j = 0; j < 4; j++) {
            int r0 = rb * 16 + (lane >> 2);
            int c = w * 32 + j * 8 + (lane & 3) * 2;
            *(float2*)&Y[r0 * XST + c]       = make_float2(acc[rb][j][0], acc[rb][j][1]);
            *(float2*)&Y[(r0 + 8) * XST + c] = make_float2(acc[rb][j][2], acc[rb][j][3]);
        }
}

// ---------------- kernel A: flags, new_mask, invalid copy, compaction ----------------
__global__ __launch_bounds__(256) void kA(const float* __restrict__ emb,
                                          const float* __restrict__ scores,
                                          const int* __restrict__ maskg,
                                          float* __restrict__ out, int n) {
    int w = threadIdx.x >> 5, lane = threadIdx.x & 31;
    int row = blockIdx.x * 8 + w;
    if (row >= n) return;
    bool saved = scores[row] > 0.f;
    bool valid = (maskg[(size_t)row * LL + (LL - 1)] == 0);
    float* omask = out + (size_t)n * DN + (size_t)n * (LL * DN);
    if (lane < LL) {
        int cur = maskg[(size_t)row * LL + lane];
        int nm = saved ? ((lane < LL - 1) ? maskg[(size_t)row * LL + lane + 1] : 0) : cur;
        omask[(size_t)row * LL + lane] = nm ? 1.f : 0.f;
    }
    if (lane == 0) {
        if (valid) { int i = atomicAdd(&g_cnts[0], 1); g_vlist[i] = row; }
        if (saved) { int i = atomicAdd(&g_cnts[1], 1); g_slist[i] = row; }
    }
    if (!valid) {
        const float4* s = (const float4*)(emb + (size_t)row * DN);
        float4* d = (float4*)(out + (size_t)row * DN);
        d[lane] = s[lane]; d[lane + 32] = s[lane + 32];
    }
}

// ---------------- kernel B: fused transformer over valid rows ----------------
// smem float offsets
#define WC_F  0            /* 256*36 = 9216 */
#define AB_F  9216         /* 128*260 = 33280 */
#define QT_F  42496        /* 32*260 = 8320 */
#define ATT_F 50816        /* 1024 */
#define SB_F  51840        /* 2560 */
#define RID_F 54400        /* 32 */
#define MSK_F 54432        /* 128 */
#define KB_SMEM (54560 * 4)

__global__ __launch_bounds__(256, 1) void kB(
    const float* __restrict__ emb, const float* __restrict__ bank,
    const int* __restrict__ maskg,
    const float* __restrict__ inw, const float* __restrict__ inb,
    const float* __restrict__ outw, const float* __restrict__ outb,
    const float* __restrict__ fc1w, const float* __restrict__ fc1b,
    const float* __restrict__ fc2w, const float* __restrict__ fc2b,
    const float* __restrict__ g1, const float* __restrict__ b1,
    const float* __restrict__ g2, const float* __restrict__ b2,
    float* __restrict__ out, int n) {
    extern __shared__ float sm[];
    float* Wc = sm + WC_F;
    float* AB = sm + AB_F;
    float* QT = sm + QT_F;
    float* att = sm + ATT_F;
    float* sb = sm + SB_F;
    int* rowid = (int*)(sm + RID_F);
    int* msk = (int*)(sm + MSK_F);

    const int cnt = g_cnts[0];
    const int tile = blockIdx.x;
    if (tile * 32 >= cnt) return;
    const int nrows = min(32, cnt - tile * 32);
    const int t = threadIdx.x, lane = t & 31, w = t >> 5;

    if (t < 32) rowid[t] = g_vlist[tile * 32 + min(t, nrows - 1)];
    sb[t]        = inb[t];
    sb[256 + t]  = inb[256 + t];
    sb[512 + t]  = inb[512 + t];
    sb[768 + t]  = outb[t];
    sb[1024 + t] = fc1b[t];
    sb[1280 + t] = fc2b[t];
    sb[1536 + t] = g1[t];
    sb[1792 + t] = b1[t];
    sb[2048 + t] = g2[t];
    sb[2304 + t] = b2[t];
    __syncthreads();
    if (t < 32 * LL) msk[t] = maskg[(size_t)rowid[t >> 2] * LL + (t & 3)];
    load_rows(emb, AB, rowid, DN, 0);

    // ---- q projection: QT = emb @ Wq^T (raw; biases folded into logits) ----
    gemmT<2>(inw, AB, Wc, QT);

    // ---- k projection, all 4 slots batched as 128 rows ----
    stage_bank(bank, AB, rowid);
    gemmT<8>(inw + DN * DN, AB, Wc, AB);       // in-place k'
    __syncthreads();                           // k' + q' visible

    // ---- logits + softmax (thread = track r, head h) ----
    {
        int r = t >> 3, h = t & 7;
        float s[LL] = {0.f, 0.f, 0.f, 0.f};
#pragma unroll 4
        for (int d0 = 0; d0 < 32; d0++) {
            int d = (d0 + t) & 31;
            int col = h * 32 + d;
            float qv = QT[r * XST + col] + sb[col];
            float kb = sb[256 + col];
#pragma unroll
            for (int l = 0; l < LL; l++)
                s[l] = fmaf(qv, AB[(l * 32 + r) * XST + col] + kb, s[l]);
        }
        const float sc = 0.17677669529663687f;
        float mx = -1e30f;
#pragma unroll
        for (int l = 0; l < LL; l++) {
            s[l] = msk[r * LL + l] ? -1e9f : s[l] * sc;
            mx = fmaxf(mx, s[l]);
        }
        float ss = 0.f;
#pragma unroll
        for (int l = 0; l < LL; l++) { s[l] = expf(s[l] - mx); ss += s[l]; }
        float inv = 1.f / ss;
#pragma unroll
        for (int l = 0; l < LL; l++) att[(r * NH + h) * LL + l] = s[l] * inv;
    }
    __syncthreads();                           // AB reads done; att visible

    // ---- v projection (batched) + att scaling + out projection (batched) ----
    stage_bank(bank, AB, rowid);
    gemmT<8>(inw + 2 * DN * DN, AB, Wc, AB);   // in-place v'
    // scale own cells: row = l*32+r, head h == c>>5 == w
#pragma unroll
    for (int rb = 0; rb < 8; rb++)
#pragma unroll
        for (int j = 0; j < 4; j++)
#pragma unroll
            for (int q = 0; q < 4; q++) {
                int row = rb * 16 + (lane >> 2) + (q >> 1) * 8;
                int c = w * 32 + j * 8 + (lane & 3) * 2 + (q & 1);
                float a = att[((row & 31) * NH + w) * LL + (row >> 5)];
                AB[row * XST + c] = a * (AB[row * XST + c] + sb[512 + c]);
            }
    gemmT<8>(outw, AB, Wc, AB);                // in-place partial attn_out (per slot)
    __syncthreads();

    // ---- reduce 4 row-groups + outb + residual + LN1 -> QT (e1) ----
    {
        int r = t >> 3, c0 = (t & 7) * 4;
        const float4* xr = (const float4*)(emb + (size_t)rowid[r] * DN);
        float4 vv[8]; float s1 = 0.f, s2 = 0.f;
#pragma unroll
        for (int j = 0; j < 8; j++) {
            int c = c0 + j * 32;
            float4 a0 = *(const float4*)&AB[r * XST + c];
            float4 a1 = *(const float4*)&AB[(32 + r) * XST + c];
            float4 a2 = *(const float4*)&AB[(64 + r) * XST + c];
            float4 a3 = *(const float4*)&AB[(96 + r) * XST + c];
            float4 bb = *(const float4*)&sb[768 + c];
            float4 rr = xr[c >> 2];
            float x0 = a0.x + a1.x + a2.x + a3.x + bb.x + rr.x;
            float x1 = a0.y + a1.y + a2.y + a3.y + bb.y + rr.y;
            float x2 = a0.z + a1.z + a2.z + a3.z + bb.z + rr.z;
            float x3 = a0.w + a1.w + a2.w + a3.w + bb.w + rr.w;
            vv[j] = make_float4(x0, x1, x2, x3);
            s1 += x0 + x1 + x2 + x3;
            s2 += x0 * x0 + x1 * x1 + x2 * x2 + x3 * x3;
        }
        s1 = segSum8(s1); s2 = segSum8(s2);
        float mu = s1 * (1.f / DN);
        float rstd = rsqrtf(fmaxf(s2 * (1.f / DN) - mu * mu, 0.f) + 1e-5f);
#pragma unroll
        for (int j = 0; j < 8; j++) {
            int c = c0 + j * 32;
            float4 gg = *(const float4*)&sb[1536 + c];
            float4 bb = *(const float4*)&sb[1792 + c];
            float4 o;
            o.x = (vv[j].x - mu) * rstd * gg.x + bb.x;
            o.y = (vv[j].y - mu) * rstd * gg.y + bb.y;
            o.z = (vv[j].z - mu) * rstd * gg.z + bb.z;
            o.w = (vv[j].w - mu) * rstd * gg.w + bb.w;
            *(float4*)&QT[r * XST + c] = o;
        }
    }

    // ---- FFN: fc1 -> relu -> fc2 (32-row GEMMs, AB rows 0..31) ----
    gemmT<2>(fc1w, QT, Wc, AB);
#pragma unroll
    for (int rb = 0; rb < 2; rb++)
#pragma unroll
        for (int j = 0; j < 4; j++)
#pragma unroll
            for (int q = 0; q < 4; q++) {
                int r = rb * 16 + (lane >> 2) + (q >> 1) * 8;
                int c = w * 32 + j * 8 + (lane & 3) * 2 + (q & 1);
                AB[r * XST + c] = fmaxf(AB[r * XST + c] + sb[1024 + c], 0.f);
            }
    gemmT<2>(fc2w, AB, Wc, AB);                // in-place
    __syncthreads();

    // ---- residual(e1) + LN2 -> scatter ----
    {
        int r = t >> 3, c0 = (t & 7) * 4;
        float4 vv[8]; float s1 = 0.f, s2 = 0.f;
#pragma unroll
        for (int j = 0; j < 8; j++) {
            int c = c0 + j * 32;
            float4 a = *(const float4*)&AB[r * XST + c];
            float4 rr = *(const float4*)&QT[r * XST + c];
            float4 bb = *(const float4*)&sb[1280 + c];
            float x0 = a.x + bb.x + rr.x, x1 = a.y + bb.y + rr.y;
            float x2 = a.z + bb.z + rr.z, x3 = a.w + bb.w + rr.w;
            vv[j] = make_float4(x0, x1, x2, x3);
            s1 += x0 + x1 + x2 + x3;
            s2 += x0 * x0 + x1 * x1 + x2 * x2 + x3 * x3;
        }
        s1 = segSum8(s1); s2 = segSum8(s2);
        float mu = s1 * (1.f / DN);
        float rstd = rsqrtf(fmaxf(s2 * (1.f / DN) - mu * mu, 0.f) + 1e-5f);
        if (r < nrows) {
            size_t row = (size_t)rowid[r];
#pragma unroll
            for (int j = 0; j < 8; j++) {
                int c = c0 + j * 32;
                float4 gg = *(const float4*)&sb[2048 + c];
                float4 bb = *(const float4*)&sb[2304 + c];
                float4 o;
                o.x = (vv[j].x - mu) * rstd * gg.x + bb.x;
                o.y = (vv[j].y - mu) * rstd * gg.y + bb.y;
                o.z = (vv[j].z - mu) * rstd * gg.z + bb.z;
                o.w = (vv[j].w - mu) * rstd * gg.w + bb.w;
                *(float4*)&out[row * DN + c] = o;
            }
        }
    }
}

// ---------------- kernel C: bank shift/copy ----------------
__global__ __launch_bounds__(256) void kC(const float* __restrict__ scores,
                                          const float* __restrict__ bank,
                                          float* __restrict__ out, int n) {
    int w = threadIdx.x >> 5, lane = threadIdx.x & 31;
    int row = blockIdx.x * 8 + w;
    if (row >= n) return;
    bool saved = scores[row] > 0.f;
    const float4* b = (const float4*)(bank + (size_t)row * (LL * DN));
    float4* ob = (float4*)(out + (size_t)n * DN + (size_t)row * (LL * DN));
#pragma unroll
    for (int l = 0; l < LL; l++) {
        int src = saved ? l + 1 : l;
        if (src < LL) {
            ob[l * 64 + lane]      = b[src * 64 + lane];
            ob[l * 64 + lane + 32] = b[src * 64 + lane + 32];
        }
    }
}

// ---------------- kernel D: save_proj (128 saved rows per tile) ----------------
#define KD_AB_F 9216
#define KD_RID_F (9216 + 33280)
#define KD_SMEM ((9216 + 33280 + 128) * 4)
__global__ __launch_bounds__(256, 1) void kD(const float* __restrict__ savew,
                                             const float* __restrict__ saveb,
                                             float* __restrict__ out, int n) {
    extern __shared__ float sm[];
    float* Wc = sm;
    float* AB = sm + KD_AB_F;
    int* rowid = (int*)(sm + KD_RID_F);

    const int cnt = g_cnts[1];
    const int tile = blockIdx.x;
    if (tile * 128 >= cnt) return;
    const int nr = min(128, cnt - tile * 128);
    const int t = threadIdx.x;
    if (t < 128) rowid[t] = g_slist[tile * 128 + min(t, nr - 1)];
    __syncthreads();
    // stage 128 new_emb rows
#pragma unroll
    for (int j = 0; j < 32; j++) {
        int f = t + j * 256;
        int row = f >> 6, v = f & 63;
        const float4* src = (const float4*)(out + (size_t)rowid[row] * DN);
        *(float4*)&AB[row * XST + v * 4] = src[v];
    }
    gemmT<8>(savew, AB, Wc, AB);               // in-place
    __syncthreads();
    float* obank = out + (size_t)n * DN;
    {
        int row = t >> 1, h = t & 1;
        if (row < nr) {
            size_t rr = (size_t)rowid[row];
            float* orow = obank + rr * (LL * DN) + (LL - 1) * DN;
#pragma unroll
            for (int j = 0; j < 32; j++) {
                int c = (h * 32 + j) * 4;
                float4 x = *(const float4*)&AB[row * XST + c];
                float4 bb = *(const float4*)&saveb[c];
                *(float4*)&orow[c] = make_float4(x.x + bb.x, x.y + bb.y,
                                                 x.z + bb.z, x.w + bb.w);
            }
        }
    }
}

// ---------------- host launch ----------------
extern "C" void kernel_launch(void* const* d_in, const int* in_sizes, int n_in,
                              void* d_out, int out_size) {
    const float* emb    = (const float*)d_in[0];
    const float* scores = (const float*)d_in[1];
    const float* bank   = (const float*)d_in[2];
    const int*   maskg  = (const int*)d_in[3];
    const float* savew = (const float*)d_in[4];
    const float* saveb = (const float*)d_in[5];
    const float* inw   = (const float*)d_in[6];
    const float* inb   = (const float*)d_in[7];
    const float* outw  = (const float*)d_in[8];
    const float* outb  = (const float*)d_in[9];
    const float* fc1w  = (const float*)d_in[10];
    const float* fc1b  = (const float*)d_in[11];
    const float* fc2w  = (const float*)d_in[12];
    const float* fc2b  = (const float*)d_in[13];
    const float* g1    = (const float*)d_in[14];
    const float* b1    = (const float*)d_in[15];
    const float* g2    = (const float*)d_in[16];
    const float* b2    = (const float*)d_in[17];
    float* out = (float*)d_out;
    int n = in_sizes[1];

    void* cntaddr = nullptr;
    cudaGetSymbolAddress(&cntaddr, g_cnts);
    cudaMemsetAsync(cntaddr, 0, 2 * sizeof(int));

    cudaFuncSetAttribute(kB, cudaFuncAttributeMaxDynamicSharedMemorySize, KB_SMEM);
    cudaFuncSetAttribute(kD, cudaFuncAttributeMaxDynamicSharedMemorySize, KD_SMEM);

    kA<<<(n + 7) / 8, 256>>>(emb, scores, maskg, out, n);
    kB<<<(n + 31) / 32, 256, KB_SMEM>>>(emb, bank, maskg, inw, inb, outw, outb,
                                        fc1w, fc1b, fc2w, fc2b, g1, b1, g2, b2,
                                        out, n);
    kC<<<(n + 7) / 8, 256>>>(scores, bank, out, n);
    kD<<<(n + 127) / 128, 256, KD_SMEM>>>(savew, saveb, out, n);
}

// round 17
// speedup vs baseline: 2.5347x; 1.0744x over previous
#include <cuda_runtime.h>
#include <stdint.h>
#include <math.h>

#define DN 256      // dim
#define LL 4        // memory bank len
#define NH 8        // heads
#define NMAX 100000
#define XST 260     // smem activation row stride (mod 32 == 4 -> conflict-free ldmatrix)
#define WST 36      // Wc row stride (mod 32 == 4)

// ---------------- device globals ----------------
__device__ int g_cnts[2];
__device__ int g_vlist[NMAX];
__device__ int g_slist[NMAX];

// ---------------- low-level helpers ----------------
__device__ __forceinline__ uint32_t s2u(const void* p) {
    uint32_t a;
    asm("{ .reg .u64 t; cvta.to.shared.u64 t, %1; cvt.u32.u64 %0, t; }" : "=r"(a) : "l"(p));
    return a;
}
__device__ __forceinline__ uint32_t tf32r(float x) {
    uint32_t u; asm("cvt.rna.tf32.f32 %0, %1;" : "=r"(u) : "f"(x)); return u;
}
__device__ __forceinline__ void sts128(uint32_t a, uint32_t x, uint32_t y, uint32_t z, uint32_t w) {
    asm volatile("st.shared.v4.b32 [%0], {%1,%2,%3,%4};" :: "r"(a), "r"(x), "r"(y), "r"(z), "r"(w));
}
__device__ __forceinline__ void ldsm4(uint32_t* r, uint32_t a) {
    asm volatile("ldmatrix.sync.aligned.m8n8.x4.shared.b16 {%0,%1,%2,%3}, [%4];"
                 : "=r"(r[0]), "=r"(r[1]), "=r"(r[2]), "=r"(r[3]) : "r"(a));
}
__device__ __forceinline__ void mma8(float* d, const uint32_t* a, const uint32_t* b) {
    asm volatile("mma.sync.aligned.m16n8k8.row.col.f32.tf32.tf32.f32 "
                 "{%0,%1,%2,%3}, {%4,%5,%6,%7}, {%8,%9}, {%0,%1,%2,%3};"
                 : "+f"(d[0]), "+f"(d[1]), "+f"(d[2]), "+f"(d[3])
                 : "r"(a[0]), "r"(a[1]), "r"(a[2]), "r"(a[3]), "r"(b[0]), "r"(b[1]));
}
__device__ __forceinline__ float segSum8(float x) {
#pragma unroll
    for (int o = 4; o > 0; o >>= 1) x += __shfl_xor_sync(0xffffffffu, x, o, 8);
    return x;
}

// Gather 32 rows of 256 floats into smem tile s[32][XST].
__device__ __forceinline__ void load_rows(const float* __restrict__ g, float* s,
                                          const int* rowid, size_t gstride, size_t goff) {
    int w = threadIdx.x >> 5, lane = threadIdx.x & 31;
#pragma unroll
    for (int i = 0; i < 4; i++) {
        int r = w * 4 + i;
        const float4* src = (const float4*)(g + (size_t)rowid[r] * gstride + goff);
        float4* dst = (float4*)(s + r * XST);
        dst[lane]      = src[lane];
        dst[lane + 32] = src[lane + 32];
    }
}

// Stage all 4 bank slots for 32 tracks as 128 rows: row = l*32 + r.
__device__ __forceinline__ void stage_bank(const float* __restrict__ bank,
                                           float* __restrict__ AB, const int* rowid) {
    int t = threadIdx.x;
#pragma unroll
    for (int j = 0; j < 32; j++) {
        int f = t + j * 256;                 // 0..8191 float4s
        int row = f >> 6, v = f & 63;
        int l = row >> 5, r = row & 31;
        const float4* src = (const float4*)(bank + (size_t)rowid[r] * (LL * DN) + (size_t)l * DN);
        *(float4*)&AB[row * XST + v * 4] = src[v];
    }
}

// Y[RB*16,256] = X[RB*16,256](stride XST) @ W^T  (W row-major [256][256] gmem, rna->tf32).
// Software-pipelined W staging: next chunk prefetched into registers during MMA.
// 256 threads; warp w owns cols [w*32, w*32+32) over all rows.
// Own-cell map: rb, j, q: r = rb*16 + (lane>>2) + (q>>1)*8 ; c = w*32 + j*8 + (lane&3)*2 + (q&1).
// Y may alias X (stores after tail barrier). Caller syncs before cross-thread reads of Y.
template<int RB>
__device__ __forceinline__ void gemmT(const float* __restrict__ Wg,
                                      const float* __restrict__ X,
                                      float* __restrict__ Wc,
                                      float* __restrict__ Y) {
    const int t = threadIdx.x, lane = t & 31, w = t >> 5;
    const uint32_t sX = s2u(X), sW = s2u(Wc);
    const uint32_t aRow = ((lane >> 3) & 1) * 8 + (lane & 7);
    const uint32_t aCol = (lane >> 4) * 4;
    const uint32_t bRow = (lane >> 4) * 8 + (lane & 7);
    const uint32_t bCol = ((lane >> 3) & 1) * 4;
    const uint32_t bB0 = sW + (((uint32_t)w * 32 + bRow) * WST + bCol) * 4;
    const uint32_t bB1 = sW + (((uint32_t)w * 32 + 16 + bRow) * WST + bCol) * 4;

    float acc[RB][4][4];
#pragma unroll
    for (int rb = 0; rb < RB; rb++)
#pragma unroll
        for (int j = 0; j < 4; j++)
#pragma unroll
            for (int q = 0; q < 4; q++) acc[rb][j][q] = 0.f;

    const int so = t >> 3, sk = (t & 7) * 4;
    // prefetch chunk 0
    float4 pf[8];
#pragma unroll
    for (int p = 0; p < 8; p++)
        pf[p] = *(const float4*)&Wg[(so + p * 32) * DN + sk];

#pragma unroll 1
    for (int kc = 0; kc < DN; kc += 32) {
        __syncthreads();                       // Wc free of previous readers
#pragma unroll
        for (int p = 0; p < 8; p++)            // commit prefetched chunk (rna->tf32)
            sts128(sW + (uint32_t)((so + p * 32) * WST + sk) * 4,
                   tf32r(pf[p].x), tf32r(pf[p].y), tf32r(pf[p].z), tf32r(pf[p].w));
        __syncthreads();
        if (kc + 32 < DN) {                    // prefetch next chunk; hidden by MMAs
#pragma unroll
            for (int p = 0; p < 8; p++)
                pf[p] = *(const float4*)&Wg[(so + p * 32) * DN + kc + 32 + sk];
        }
#pragma unroll
        for (int ks = 0; ks < 32; ks += 8) {
            uint32_t b0[4], b1[4];
            ldsm4(b0, bB0 + (uint32_t)ks * 4);
            ldsm4(b1, bB1 + (uint32_t)ks * 4);
#pragma unroll
            for (int rb = 0; rb < RB; rb++) {
                uint32_t a[4];
                ldsm4(a, sX + (uint32_t)((rb * 16 + aRow) * XST + aCol + kc + ks) * 4);
                mma8(acc[rb][0], a, b0);   mma8(acc[rb][1], a, b0 + 2);
                mma8(acc[rb][2], a, b1);   mma8(acc[rb][3], a, b1 + 2);
            }
        }
    }
    __syncthreads();                           // all X reads done; Y may alias X
#pragma unroll
    for (int rb = 0; rb < RB; rb++)
#pragma unroll
        for (int j = 0; j < 4; j++) {
            int r0 = rb * 16 + (lane >> 2);
            int c = w * 32 + j * 8 + (lane & 3) * 2;
            *(float2*)&Y[r0 * XST + c]       = make_float2(acc[rb][j][0], acc[rb][j][1]);
            *(float2*)&Y[(r0 + 8) * XST + c] = make_float2(acc[rb][j][2], acc[rb][j][3]);
        }
}

// ---------------- kernel A: flags, new_mask, invalid copy, compaction, bank shift ----
__global__ __launch_bounds__(256) void kA(const float* __restrict__ emb,
                                          const float* __restrict__ scores,
                                          const int* __restrict__ maskg,
                                          const float* __restrict__ bank,
                                          float* __restrict__ out, int n) {
    int w = threadIdx.x >> 5, lane = threadIdx.x & 31;
    int row = blockIdx.x * 8 + w;
    if (row >= n) return;
    bool saved = scores[row] > 0.f;
    bool valid = (maskg[(size_t)row * LL + (LL - 1)] == 0);
    float* omask = out + (size_t)n * DN + (size_t)n * (LL * DN);
    if (lane < LL) {
        int cur = maskg[(size_t)row * LL + lane];
        int nm = saved ? ((lane < LL - 1) ? maskg[(size_t)row * LL + lane + 1] : 0) : cur;
        omask[(size_t)row * LL + lane] = nm ? 1.f : 0.f;
    }
    if (lane == 0) {
        if (valid) { int i = atomicAdd(&g_cnts[0], 1); g_vlist[i] = row; }
        if (saved) { int i = atomicAdd(&g_cnts[1], 1); g_slist[i] = row; }
    }
    if (!valid) {
        const float4* s = (const float4*)(emb + (size_t)row * DN);
        float4* d = (float4*)(out + (size_t)row * DN);
        d[lane] = s[lane]; d[lane + 32] = s[lane + 32];
    }
    // bank shift/copy (slot L-1 for saved rows is overwritten later by kD)
    const float4* b = (const float4*)(bank + (size_t)row * (LL * DN));
    float4* ob = (float4*)(out + (size_t)n * DN + (size_t)row * (LL * DN));
#pragma unroll
    for (int l = 0; l < LL; l++) {
        int src = saved ? l + 1 : l;
        if (src < LL) {
            ob[l * 64 + lane]      = b[src * 64 + lane];
            ob[l * 64 + lane + 32] = b[src * 64 + lane + 32];
        }
    }
}

// ---------------- kernel B: fused transformer over valid rows ----------------
// smem float offsets
#define WC_F  0            /* 256*36 = 9216 */
#define AB_F  9216         /* 128*260 = 33280 */
#define QT_F  42496        /* 32*260 = 8320 */
#define ATT_F 50816        /* 1024 */
#define SB_F  51840        /* 2560 */
#define RID_F 54400        /* 32 */
#define MSK_F 54432        /* 128 */
#define KB_SMEM (54560 * 4)

__global__ __launch_bounds__(256, 1) void kB(
    const float* __restrict__ emb, const float* __restrict__ bank,
    const int* __restrict__ maskg,
    const float* __restrict__ inw, const float* __restrict__ inb,
    const float* __restrict__ outw, const float* __restrict__ outb,
    const float* __restrict__ fc1w, const float* __restrict__ fc1b,
    const float* __restrict__ fc2w, const float* __restrict__ fc2b,
    const float* __restrict__ g1, const float* __restrict__ b1,
    const float* __restrict__ g2, const float* __restrict__ b2,
    float* __restrict__ out, int n) {
    extern __shared__ float sm[];
    float* Wc = sm + WC_F;
    float* AB = sm + AB_F;
    float* QT = sm + QT_F;
    float* att = sm + ATT_F;
    float* sb = sm + SB_F;
    int* rowid = (int*)(sm + RID_F);
    int* msk = (int*)(sm + MSK_F);

    const int cnt = g_cnts[0];
    const int tile = blockIdx.x;
    if (tile * 32 >= cnt) return;
    const int nrows = min(32, cnt - tile * 32);
    const int t = threadIdx.x, lane = t & 31, w = t >> 5;

    if (t < 32) rowid[t] = g_vlist[tile * 32 + min(t, nrows - 1)];
    sb[t]        = inb[t];
    sb[256 + t]  = inb[256 + t];
    sb[512 + t]  = inb[512 + t];
    sb[768 + t]  = outb[t];
    sb[1024 + t] = fc1b[t];
    sb[1280 + t] = fc2b[t];
    sb[1536 + t] = g1[t];
    sb[1792 + t] = b1[t];
    sb[2048 + t] = g2[t];
    sb[2304 + t] = b2[t];
    __syncthreads();
    if (t < 32 * LL) msk[t] = maskg[(size_t)rowid[t >> 2] * LL + (t & 3)];
    load_rows(emb, AB, rowid, DN, 0);

    // ---- q projection: QT = emb @ Wq^T (raw; biases folded into logits) ----
    gemmT<2>(inw, AB, Wc, QT);

    // ---- k projection, all 4 slots batched as 128 rows ----
    stage_bank(bank, AB, rowid);
    gemmT<8>(inw + DN * DN, AB, Wc, AB);       // in-place k'
    __syncthreads();                           // k' + q' visible

    // ---- logits + softmax (thread = track r, head h) ----
    {
        int r = t >> 3, h = t & 7;
        float s[LL] = {0.f, 0.f, 0.f, 0.f};
#pragma unroll 4
        for (int d0 = 0; d0 < 32; d0++) {
            int d = (d0 + t) & 31;
            int col = h * 32 + d;
            float qv = QT[r * XST + col] + sb[col];
            float kb = sb[256 + col];
#pragma unroll
            for (int l = 0; l < LL; l++)
                s[l] = fmaf(qv, AB[(l * 32 + r) * XST + col] + kb, s[l]);
        }
        const float sc = 0.17677669529663687f;
        float mx = -1e30f;
#pragma unroll
        for (int l = 0; l < LL; l++) {
            s[l] = msk[r * LL + l] ? -1e9f : s[l] * sc;
            mx = fmaxf(mx, s[l]);
        }
        float ss = 0.f;
#pragma unroll
        for (int l = 0; l < LL; l++) { s[l] = expf(s[l] - mx); ss += s[l]; }
        float inv = 1.f / ss;
#pragma unroll
        for (int l = 0; l < LL; l++) att[(r * NH + h) * LL + l] = s[l] * inv;
    }
    __syncthreads();                           // AB reads done; att visible

    // ---- v projection (batched) + att scaling + out projection (batched) ----
    stage_bank(bank, AB, rowid);
    gemmT<8>(inw + 2 * DN * DN, AB, Wc, AB);   // in-place v'
    // scale own cells: row = l*32+r, head h == c>>5 == w
#pragma unroll
    for (int rb = 0; rb < 8; rb++)
#pragma unroll
        for (int j = 0; j < 4; j++)
#pragma unroll
            for (int q = 0; q < 4; q++) {
                int row = rb * 16 + (lane >> 2) + (q >> 1) * 8;
                int c = w * 32 + j * 8 + (lane & 3) * 2 + (q & 1);
                float a = att[((row & 31) * NH + w) * LL + (row >> 5)];
                AB[row * XST + c] = a * (AB[row * XST + c] + sb[512 + c]);
            }
    gemmT<8>(outw, AB, Wc, AB);                // in-place partial attn_out (per slot)
    __syncthreads();

    // ---- reduce 4 row-groups + outb + residual + LN1 -> QT (e1) ----
    {
        int r = t >> 3, c0 = (t & 7) * 4;
        const float4* xr = (const float4*)(emb + (size_t)rowid[r] * DN);
        float4 vv[8]; float s1 = 0.f, s2 = 0.f;
#pragma unroll
        for (int j = 0; j < 8; j++) {
            int c = c0 + j * 32;
            float4 a0 = *(const float4*)&AB[r * XST + c];
            float4 a1 = *(const float4*)&AB[(32 + r) * XST + c];
            float4 a2 = *(const float4*)&AB[(64 + r) * XST + c];
            float4 a3 = *(const float4*)&AB[(96 + r) * XST + c];
            float4 bb = *(const float4*)&sb[768 + c];
            float4 rr = xr[c >> 2];
            float x0 = a0.x + a1.x + a2.x + a3.x + bb.x + rr.x;
            float x1 = a0.y + a1.y + a2.y + a3.y + bb.y + rr.y;
            float x2 = a0.z + a1.z + a2.z + a3.z + bb.z + rr.z;
            float x3 = a0.w + a1.w + a2.w + a3.w + bb.w + rr.w;
            vv[j] = make_float4(x0, x1, x2, x3);
            s1 += x0 + x1 + x2 + x3;
            s2 += x0 * x0 + x1 * x1 + x2 * x2 + x3 * x3;
        }
        s1 = segSum8(s1); s2 = segSum8(s2);
        float mu = s1 * (1.f / DN);
        float rstd = rsqrtf(fmaxf(s2 * (1.f / DN) - mu * mu, 0.f) + 1e-5f);
#pragma unroll
        for (int j = 0; j < 8; j++) {
            int c = c0 + j * 32;
            float4 gg = *(const float4*)&sb[1536 + c];
            float4 bb = *(const float4*)&sb[1792 + c];
            float4 o;
            o.x = (vv[j].x - mu) * rstd * gg.x + bb.x;
            o.y = (vv[j].y - mu) * rstd * gg.y + bb.y;
            o.z = (vv[j].z - mu) * rstd * gg.z + bb.z;
            o.w = (vv[j].w - mu) * rstd * gg.w + bb.w;
            *(float4*)&QT[r * XST + c] = o;
        }
    }

    // ---- FFN: fc1 -> relu -> fc2 (32-row GEMMs) ----
    gemmT<2>(fc1w, QT, Wc, AB);
#pragma unroll
    for (int rb = 0; rb < 2; rb++)
#pragma unroll
        for (int j = 0; j < 4; j++)
#pragma unroll
            for (int q = 0; q < 4; q++) {
                int r = rb * 16 + (lane >> 2) + (q >> 1) * 8;
                int c = w * 32 + j * 8 + (lane & 3) * 2 + (q & 1);
                AB[r * XST + c] = fmaxf(AB[r * XST + c] + sb[1024 + c], 0.f);
            }
    gemmT<2>(fc2w, AB, Wc, AB);                // in-place
    __syncthreads();

    // ---- residual(e1) + LN2 -> scatter ----
    {
        int r = t >> 3, c0 = (t & 7) * 4;
        float4 vv[8]; float s1 = 0.f, s2 = 0.f;
#pragma unroll
        for (int j = 0; j < 8; j++) {
            int c = c0 + j * 32;
            float4 a = *(const float4*)&AB[r * XST + c];
            float4 rr = *(const float4*)&QT[r * XST + c];
            float4 bb = *(const float4*)&sb[1280 + c];
            float x0 = a.x + bb.x + rr.x, x1 = a.y + bb.y + rr.y;
            float x2 = a.z + bb.z + rr.z, x3 = a.w + bb.w + rr.w;
            vv[j] = make_float4(x0, x1, x2, x3);
            s1 += x0 + x1 + x2 + x3;
            s2 += x0 * x0 + x1 * x1 + x2 * x2 + x3 * x3;
        }
        s1 = segSum8(s1); s2 = segSum8(s2);
        float mu = s1 * (1.f / DN);
        float rstd = rsqrtf(fmaxf(s2 * (1.f / DN) - mu * mu, 0.f) + 1e-5f);
        if (r < nrows) {
            size_t row = (size_t)rowid[r];
#pragma unroll
            for (int j = 0; j < 8; j++) {
                int c = c0 + j * 32;
                float4 gg = *(const float4*)&sb[2048 + c];
                float4 bb = *(const float4*)&sb[2304 + c];
                float4 o;
                o.x = (vv[j].x - mu) * rstd * gg.x + bb.x;
                o.y = (vv[j].y - mu) * rstd * gg.y + bb.y;
                o.z = (vv[j].z - mu) * rstd * gg.z + bb.z;
                o.w = (vv[j].w - mu) * rstd * gg.w + bb.w;
                *(float4*)&out[row * DN + c] = o;
            }
        }
    }
}

// ---------------- kernel D: save_proj (128 saved rows per tile) ----------------
#define KD_AB_F 9216
#define KD_RID_F (9216 + 33280)
#define KD_SMEM ((9216 + 33280 + 128) * 4)
__global__ __launch_bounds__(256, 1) void kD(const float* __restrict__ savew,
                                             const float* __restrict__ saveb,
                                             float* __restrict__ out, int n) {
    extern __shared__ float sm[];
    float* Wc = sm;
    float* AB = sm + KD_AB_F;
    int* rowid = (int*)(sm + KD_RID_F);

    const int cnt = g_cnts[1];
    const int tile = blockIdx.x;
    if (tile * 128 >= cnt) return;
    const int nr = min(128, cnt - tile * 128);
    const int t = threadIdx.x;
    if (t < 128) rowid[t] = g_slist[tile * 128 + min(t, nr - 1)];
    __syncthreads();
    // stage 128 new_emb rows
#pragma unroll
    for (int j = 0; j < 32; j++) {
        int f = t + j * 256;
        int row = f >> 6, v = f & 63;
        const float4* src = (const float4*)(out + (size_t)rowid[row] * DN);
        *(float4*)&AB[row * XST + v * 4] = src[v];
    }
    gemmT<8>(savew, AB, Wc, AB);               // in-place
    __syncthreads();
    float* obank = out + (size_t)n * DN;
    {
        int row = t >> 1, h = t & 1;
        if (row < nr) {
            size_t rr = (size_t)rowid[row];
            float* orow = obank + rr * (LL * DN) + (LL - 1) * DN;
#pragma unroll
            for (int j = 0; j < 32; j++) {
                int c = (h * 32 + j) * 4;
                float4 x = *(const float4*)&AB[row * XST + c];
                float4 bb = *(const float4*)&saveb[c];
                *(float4*)&orow[c] = make_float4(x.x + bb.x, x.y + bb.y,
                                                 x.z + bb.z, x.w + bb.w);
            }
        }
    }
}

// ---------------- host launch ----------------
extern "C" void kernel_launch(void* const* d_in, const int* in_sizes, int n_in,
                              void* d_out, int out_size) {
    const float* emb    = (const float*)d_in[0];
    const float* scores = (const float*)d_in[1];
    const float* bank   = (const float*)d_in[2];
    const int*   maskg  = (const int*)d_in[3];
    const float* savew = (const float*)d_in[4];
    const float* saveb = (const float*)d_in[5];
    const float* inw   = (const float*)d_in[6];
    const float* inb   = (const float*)d_in[7];
    const float* outw  = (const float*)d_in[8];
    const float* outb  = (const float*)d_in[9];
    const float* fc1w  = (const float*)d_in[10];
    const float* fc1b  = (const float*)d_in[11];
    const float* fc2w  = (const float*)d_in[12];
    const float* fc2b  = (const float*)d_in[13];
    const float* g1    = (const float*)d_in[14];
    const float* b1    = (const float*)d_in[15];
    const float* g2    = (const float*)d_in[16];
    const float* b2    = (const float*)d_in[17];
    float* out = (float*)d_out;
    int n = in_sizes[1];

    void* cntaddr = nullptr;
    cudaGetSymbolAddress(&cntaddr, g_cnts);
    cudaMemsetAsync(cntaddr, 0, 2 * sizeof(int));

    cudaFuncSetAttribute(kB, cudaFuncAttributeMaxDynamicSharedMemorySize, KB_SMEM);
    cudaFuncSetAttribute(kD, cudaFuncAttributeMaxDynamicSharedMemorySize, KD_SMEM);

    kA<<<(n + 7) / 8, 256>>>(emb, scores, maskg, bank, out, n);
    kB<<<(n + 31) / 32, 256, KB_SMEM>>>(emb, bank, maskg, inw, inb, outw, outb,
                                        fc1w, fc1b, fc2w, fc2b, g1, b1, g2, b2,
                                        out, n);
    kD<<<(n + 127) / 128, 256, KD_SMEM>>>(savew, saveb, out, n);
}